// round 13
// baseline (speedup 1.0000x reference)
#include <cuda_runtime.h>
#include <cuda_bf16.h>
#include <cstdint>

// Problem constants
#define DIN   128
#define DOUT  128
#define DEG   48
#define KSEL  32
#define NPAD  50048

// Interleaved split storage: per node 256 bf16 = [128 hi][128 lo] (512 B row)
__device__ __nv_bfloat16 g_xs[(size_t)NPAD * 256];
__device__ __nv_bfloat16 g_wThi[128 * 128];            // W^T hi, [n][k]
__device__ __nv_bfloat16 g_wTlo[128 * 128];            // W^T lo, [n][k]

// ---------------------------------------------------------------------------
// Common helpers
// ---------------------------------------------------------------------------
__device__ __forceinline__ uint32_t smem_u32(const void* p) {
    uint32_t a;
    asm("{ .reg .u64 t; cvta.to.shared.u64 t, %1; cvt.u32.u64 %0, t; }" : "=r"(a) : "l"(p));
    return a;
}

__device__ __forceinline__ void ldmatrix_x4(uint32_t* r, uint32_t addr) {
    asm volatile("ldmatrix.sync.aligned.m8n8.x4.shared.b16 {%0,%1,%2,%3}, [%4];"
                 : "=r"(r[0]), "=r"(r[1]), "=r"(r[2]), "=r"(r[3]) : "r"(addr));
}

__device__ __forceinline__ void ldmatrix_x4_trans(uint32_t* r, uint32_t addr) {
    asm volatile("ldmatrix.sync.aligned.m8n8.x4.trans.shared.b16 {%0,%1,%2,%3}, [%4];"
                 : "=r"(r[0]), "=r"(r[1]), "=r"(r[2]), "=r"(r[3]) : "r"(addr));
}

__device__ __forceinline__ void mma_bf16(float* c, const uint32_t* a, const uint32_t* b) {
    asm volatile(
        "mma.sync.aligned.m16n8k16.row.col.f32.bf16.bf16.f32 "
        "{%0,%1,%2,%3}, {%4,%5,%6,%7}, {%8,%9}, {%0,%1,%2,%3};"
        : "+f"(c[0]), "+f"(c[1]), "+f"(c[2]), "+f"(c[3])
        : "r"(a[0]), "r"(a[1]), "r"(a[2]), "r"(a[3]), "r"(b[0]), "r"(b[1]));
}

__device__ __forceinline__ float sqrt_approx(float x) {
    float y;
    asm("sqrt.approx.f32 %0, %1;" : "=f"(y) : "f"(x));
    return y;
}

// PDL controls
__device__ __forceinline__ void pdl_wait() {
    asm volatile("griddepcontrol.wait;" ::: "memory");
}
__device__ __forceinline__ void pdl_launch_dependents() {
    asm volatile("griddepcontrol.launch_dependents;" ::: "memory");
}

// Truncation split: hi = top-16 bits of fp32, lo = rn-bf16 of (x - hi).
__device__ __forceinline__ void split4(float4 v, uint2& hp, uint2& lp) {
    uint32_t ax = __float_as_uint(v.x), ay = __float_as_uint(v.y);
    uint32_t az = __float_as_uint(v.z), aw = __float_as_uint(v.w);
    hp.x = __byte_perm(ax, ay, 0x7632);
    hp.y = __byte_perm(az, aw, 0x7632);
    float lx = v.x - __uint_as_float(ax & 0xffff0000u);
    float ly = v.y - __uint_as_float(ay & 0xffff0000u);
    float lz = v.z - __uint_as_float(az & 0xffff0000u);
    float lw = v.w - __uint_as_float(aw & 0xffff0000u);
    asm("cvt.rn.bf16x2.f32 %0, %1, %2;" : "=r"(lp.x) : "f"(ly), "f"(lx));
    asm("cvt.rn.bf16x2.f32 %0, %1, %2;" : "=r"(lp.y) : "f"(lw), "f"(lz));
}

__device__ __forceinline__ void split2(float x, float y, uint32_t& hp, uint32_t& lp) {
    uint32_t ax = __float_as_uint(x), ay = __float_as_uint(y);
    hp = __byte_perm(ax, ay, 0x7632);
    float lx = x - __uint_as_float(ax & 0xffff0000u);
    float ly = y - __uint_as_float(ay & 0xffff0000u);
    asm("cvt.rn.bf16x2.f32 %0, %1, %2;" : "=r"(lp) : "f"(ly), "f"(lx));
}

// ---------------------------------------------------------------------------
// Kernel 0: transpose + split W -> g_wThi/g_wTlo  ([n][k] bf16)
// ---------------------------------------------------------------------------
__global__ __launch_bounds__(256) void wsplit_kernel(const float* __restrict__ W)
{
    int idx = blockIdx.x * 256 + threadIdx.x;
    int k = idx >> 7, nn = idx & 127;
    float v = W[k * 128 + nn];
    uint32_t b = __float_as_uint(v);
    uint32_t hbits = b & 0xffff0000u;
    float lo = v - __uint_as_float(hbits);
    g_wThi[nn * 128 + k] = __ushort_as_bfloat16((unsigned short)(hbits >> 16));
    g_wTlo[nn * 128 + k] = __float2bfloat16_rn(lo);
    pdl_launch_dependents();
}

// ---------------------------------------------------------------------------
// Kernel A: x = feat @ W via bf16 3-pass mma.sync; epilogue -> interleaved g_xs
// PDL: waits on wsplit only before first g_wT read; signals node at end.
// ---------------------------------------------------------------------------
#define GAP 40   // bf16 smem pitch (80 B), ldmatrix conflict-free

__global__ __launch_bounds__(256) void gemm_kernel(const float* __restrict__ feat,
                                                   int n)
{
    __shared__ __align__(16) __nv_bfloat16 sa_h[128 * GAP];
    __shared__ __align__(16) __nv_bfloat16 sa_l[128 * GAP];
    __shared__ __align__(16) __nv_bfloat16 sb_h[128 * GAP];
    __shared__ __align__(16) __nv_bfloat16 sb_l[128 * GAP];

    const int tid  = threadIdx.x;
    const int lane = tid & 31;
    const int wrp  = tid >> 5;
    const int row0 = blockIdx.x * 128;

    const int m0 = (wrp & 1) * 64;
    const int n0 = (wrp >> 1) * 32;
    const int rsel = lane >> 3, rin = lane & 7;

    const uint32_t sah = smem_u32(sa_h), sal = smem_u32(sa_l);
    const uint32_t sbh = smem_u32(sb_h), sbl = smem_u32(sb_l);

    float acc[4][4][4];
#pragma unroll
    for (int mt = 0; mt < 4; ++mt)
#pragma unroll
        for (int nt = 0; nt < 4; ++nt)
#pragma unroll
            for (int i = 0; i < 4; ++i) acc[mt][nt][i] = 0.0f;

    for (int kt = 0; kt < 4; ++kt) {
#pragma unroll
        for (int i = 0; i < 4; ++i) {
            int idx = tid + i * 256;
            int r = idx >> 3, q = idx & 7;
            int rg = row0 + r; if (rg > n - 1) rg = n - 1;
            float4 v = *(const float4*)&feat[(size_t)rg * DIN + kt * 32 + q * 4];
            uint2 hp, lp;
            split4(v, hp, lp);
            *(uint2*)&sa_h[r * GAP + q * 4] = hp;
            *(uint2*)&sa_l[r * GAP + q * 4] = lp;
        }
        if (kt == 0) pdl_wait();   // first g_wT read below
#pragma unroll
        for (int i = 0; i < 2; ++i) {
            int idx = tid + i * 256;
            int r = idx >> 2, q = idx & 3;
            *(uint4*)&sb_h[r * GAP + q * 8] =
                *(const uint4*)&g_wThi[r * 128 + kt * 32 + q * 8];
            *(uint4*)&sb_l[r * GAP + q * 8] =
                *(const uint4*)&g_wTlo[r * 128 + kt * 32 + q * 8];
        }
        __syncthreads();

#pragma unroll
        for (int kc = 0; kc < 2; ++kc) {
            const uint32_t kadd = kc * 32;
            uint32_t bh[8], bl[8];
#pragma unroll
            for (int h = 0; h < 2; ++h) {
                uint32_t boff = (uint32_t)((n0 + h * 16 + (rsel >> 1) * 8 + rin) * GAP
                                           + (rsel & 1) * 8) * 2 + kadd;
                ldmatrix_x4(&bh[h * 4], sbh + boff);
                ldmatrix_x4(&bl[h * 4], sbl + boff);
            }
#pragma unroll
            for (int mt = 0; mt < 4; ++mt) {
                uint32_t aoff = (uint32_t)((m0 + mt * 16 + (rsel & 1) * 8 + rin) * GAP
                                           + (rsel >> 1) * 8) * 2 + kadd;
                uint32_t ah[4], al[4];
                ldmatrix_x4(ah, sah + aoff);
                ldmatrix_x4(al, sal + aoff);
#pragma unroll
                for (int nt = 0; nt < 4; ++nt) {
                    mma_bf16(acc[mt][nt], ah, &bh[nt * 2]);
                    mma_bf16(acc[mt][nt], ah, &bl[nt * 2]);
                    mma_bf16(acc[mt][nt], al, &bh[nt * 2]);
                }
            }
        }
        __syncthreads();
    }

    // epilogue: trunc-split, store interleaved [128 hi][128 lo] per node row
#pragma unroll
    for (int mt = 0; mt < 4; ++mt) {
        int ra = row0 + m0 + mt * 16 + (lane >> 2);
#pragma unroll
        for (int nt = 0; nt < 4; ++nt) {
            int cb = n0 + nt * 8 + 2 * (lane & 3);
            uint32_t hp, lp;
            split2(acc[mt][nt][0], acc[mt][nt][1], hp, lp);
            *(uint32_t*)&g_xs[(size_t)ra * 256 + cb]       = hp;
            *(uint32_t*)&g_xs[(size_t)ra * 256 + 128 + cb] = lp;
            split2(acc[mt][nt][2], acc[mt][nt][3], hp, lp);
            *(uint32_t*)&g_xs[(size_t)(ra + 8) * 256 + cb]       = hp;
            *(uint32_t*)&g_xs[(size_t)(ra + 8) * 256 + 128 + cb] = lp;
        }
    }
    pdl_launch_dependents();
}

// ---------------------------------------------------------------------------
// Kernel B: topk (register rank, pre-dependency), cp.async gather, symmetric
//           3-tile Gram, in-fragment dist, fast softmax, X^T mma agg.
//           1 CTA/node, 128 threads. PDL: waits on gemm only before gather.
// ---------------------------------------------------------------------------
#define BPITCH 136

__global__ __launch_bounds__(128) void node_kernel(const float* __restrict__ ew,
                                                   const int*   __restrict__ nbr,
                                                   const float* __restrict__ bias,
                                                   float*       __restrict__ out,
                                                   int n)
{
    __shared__ __align__(16) __nv_bfloat16 xhi[32 * BPITCH];
    __shared__ __align__(16) __nv_bfloat16 xlo[32 * BPITCH];
    __shared__ float selw[32];
    __shared__ int   selid[32];
    __shared__ float ssq[32];
    __shared__ float sdA[32];
    __shared__ float sdB[32];
    __shared__ __align__(4) unsigned short srelh[32];
    __shared__ __align__(4) unsigned short srell[32];

    const int node = blockIdx.x;
    const int tid  = threadIdx.x;
    const int lane = tid & 31;
    const int wrp  = tid >> 5;

    // --- top-32 of 49 (independent of gemm output -> runs under PDL overlap) ---
    if (tid < DEG + 1) {
        float v; int myid;
        if (tid < DEG) {
            v    = ew[(size_t)node * DEG + tid];
            myid = nbr[(size_t)node * DEG + tid];
        } else {
            v = 1.0f; myid = node;
        }
        int rank = (1.0f > v) ? 1 : 0;   // self-loop j=48: j<tid never for tid<=48
        const float4* row = (const float4*)(ew + (size_t)node * DEG);
#pragma unroll
        for (int c = 0; c < 12; ++c) {
            float4 w4 = row[c];
            int j0 = c * 4;
            rank += (w4.x > v) || (w4.x == v && (j0 + 0) < tid);
            rank += (w4.y > v) || (w4.y == v && (j0 + 1) < tid);
            rank += (w4.z > v) || (w4.z == v && (j0 + 2) < tid);
            rank += (w4.w > v) || (w4.w == v && (j0 + 3) < tid);
        }
        if (rank < KSEL) { selw[rank] = v; selid[rank] = myid; }
    }
    __syncthreads();

    pdl_wait();   // g_xs must be complete from here on

    // --- gather via cp.async: 1 row = 512B = 32 lanes x 16B ---
    {
        const int r0 = wrp * 8;
        const uint32_t hbase0 = smem_u32(xhi);
        const uint32_t lbase0 = smem_u32(xlo);
        const uint32_t dbase  = (lane < 16 ? hbase0 : lbase0) + (lane & 15) * 16;
#pragma unroll
        for (int r = 0; r < 8; ++r) {
            const int row = r0 + r;
            const char* src = (const char*)g_xs + (size_t)selid[row] * 512 + lane * 16;
            uint32_t dst = dbase + (uint32_t)(row * (BPITCH * 2));
            asm volatile("cp.async.ca.shared.global [%0], [%1], 16;"
                         :: "r"(dst), "l"(src));
        }
        asm volatile("cp.async.commit_group;");
        asm volatile("cp.async.wait_group 0;");
    }
    __syncthreads();

    // --- Gram, 3 tiles: w0 diag(0,0) A=B aliased, w1 diag(16,16), w2 offdiag ---
    const uint32_t hbase = smem_u32(xhi);
    const uint32_t lbase = smem_u32(xlo);
    const int p = lane >> 2;
    const int q = lane & 3;
    float c0f[4] = {0.f, 0.f, 0.f, 0.f};
    float c1f[4] = {0.f, 0.f, 0.f, 0.f};

    if (wrp < 2) {
        const int m0 = wrp * 16;
        const int rsel = lane >> 3, rin = lane & 7;
        const uint32_t a_off = (uint32_t)((m0 + (rsel & 1) * 8 + rin) * BPITCH
                                          + (rsel >> 1) * 8) * 2;
#pragma unroll
        for (int kc = 0; kc < 8; ++kc) {
            uint32_t ah[4], al[4];
            ldmatrix_x4(ah, hbase + a_off + kc * 32);
            ldmatrix_x4(al, lbase + a_off + kc * 32);
            uint32_t bh0[2] = {ah[0], ah[2]}, bh1[2] = {ah[1], ah[3]};
            uint32_t bl0[2] = {al[0], al[2]}, bl1[2] = {al[1], al[3]};
            mma_bf16(c0f, ah, bh0); mma_bf16(c0f, ah, bl0); mma_bf16(c0f, al, bh0);
            mma_bf16(c1f, ah, bh1); mma_bf16(c1f, ah, bl1); mma_bf16(c1f, al, bh1);
        }
        if (p == 2 * q)     { ssq[m0 + p] = c0f[0]; ssq[m0 + p + 8] = c1f[2]; }
        if (p == 2 * q + 1) { ssq[m0 + p] = c0f[1]; ssq[m0 + p + 8] = c1f[3]; }
    } else if (wrp == 2) {
        const int rsel = lane >> 3, rin = lane & 7;
        const uint32_t a_off = (uint32_t)(((rsel & 1) * 8 + rin) * BPITCH
                                          + (rsel >> 1) * 8) * 2;
        const uint32_t b_off = (uint32_t)((16 + (rsel >> 1) * 8 + rin) * BPITCH
                                          + (rsel & 1) * 8) * 2;
#pragma unroll
        for (int kc = 0; kc < 8; ++kc) {
            uint32_t ah[4], al[4], bh[4], bl[4];
            ldmatrix_x4(ah, hbase + a_off + kc * 32);
            ldmatrix_x4(al, lbase + a_off + kc * 32);
            ldmatrix_x4(bh, hbase + b_off + kc * 32);
            ldmatrix_x4(bl, lbase + b_off + kc * 32);
            mma_bf16(c0f, ah, &bh[0]); mma_bf16(c0f, ah, &bl[0]); mma_bf16(c0f, al, &bh[0]);
            mma_bf16(c1f, ah, &bh[2]); mma_bf16(c1f, ah, &bl[2]); mma_bf16(c1f, al, &bh[2]);
        }
    }
    __syncthreads();   // ssq visible to all

    // --- dist partials ---
    if (wrp < 2) {
        const int m0 = wrp * 16;
        const int b0 = m0 + 2 * q, b1 = b0 + 1, b2 = b0 + 8, b3 = b2 + 1;
        const float w0 = selw[b0], w1 = selw[b1], w2 = selw[b2], w3 = selw[b3];
        const float s0 = ssq[b0], s1 = ssq[b1], s2 = ssq[b2], s3 = ssq[b3];
        const float sqa  = ssq[m0 + p];
        const float sqa8 = ssq[m0 + p + 8];

        float d, part = 0.f, part8 = 0.f;
        d = sqa  + s0 - 2.f * c0f[0]; part  = fmaf(w0, (d > 0.f) ? sqrt_approx(d) : 0.f, part);
        d = sqa  + s1 - 2.f * c0f[1]; part  = fmaf(w1, (d > 0.f) ? sqrt_approx(d) : 0.f, part);
        d = sqa  + s2 - 2.f * c1f[0]; part  = fmaf(w2, (d > 0.f) ? sqrt_approx(d) : 0.f, part);
        d = sqa  + s3 - 2.f * c1f[1]; part  = fmaf(w3, (d > 0.f) ? sqrt_approx(d) : 0.f, part);
        d = sqa8 + s0 - 2.f * c0f[2]; part8 = fmaf(w0, (d > 0.f) ? sqrt_approx(d) : 0.f, part8);
        d = sqa8 + s1 - 2.f * c0f[3]; part8 = fmaf(w1, (d > 0.f) ? sqrt_approx(d) : 0.f, part8);
        d = sqa8 + s2 - 2.f * c1f[2]; part8 = fmaf(w2, (d > 0.f) ? sqrt_approx(d) : 0.f, part8);
        d = sqa8 + s3 - 2.f * c1f[3]; part8 = fmaf(w3, (d > 0.f) ? sqrt_approx(d) : 0.f, part8);

        part  += __shfl_down_sync(0xffffffffu, part, 2);
        part  += __shfl_down_sync(0xffffffffu, part, 1);
        part8 += __shfl_down_sync(0xffffffffu, part8, 2);
        part8 += __shfl_down_sync(0xffffffffu, part8, 1);
        if (q == 0) { sdA[m0 + p] = part; sdA[m0 + p + 8] = part8; }
    } else if (wrp == 2) {
        const int cA = 16 + 2 * q, cB = cA + 1, cC = cA + 8, cD = cC + 1;
        const float wA = selw[cA], wB = selw[cB], wC = selw[cC], wD = selw[cD];
        const float sA = ssq[cA], sB = ssq[cB], sC = ssq[cC], sD = ssq[cD];
        const float sqa  = ssq[p];
        const float sqa8 = ssq[p + 8];
        const float wp   = selw[p];
        const float wp8  = selw[p + 8];

        float d;
        d = sqa  + sA - 2.f * c0f[0]; float dpA = (d > 0.f) ? sqrt_approx(d) : 0.f;
        d = sqa  + sB - 2.f * c0f[1]; float dpB = (d > 0.f) ? sqrt_approx(d) : 0.f;
        d = sqa  + sC - 2.f * c1f[0]; float dpC = (d > 0.f) ? sqrt_approx(d) : 0.f;
        d = sqa  + sD - 2.f * c1f[1]; float dpD = (d > 0.f) ? sqrt_approx(d) : 0.f;
        d = sqa8 + sA - 2.f * c0f[2]; float d8A = (d > 0.f) ? sqrt_approx(d) : 0.f;
        d = sqa8 + sB - 2.f * c0f[3]; float d8B = (d > 0.f) ? sqrt_approx(d) : 0.f;
        d = sqa8 + sC - 2.f * c1f[2]; float d8C = (d > 0.f) ? sqrt_approx(d) : 0.f;
        d = sqa8 + sD - 2.f * c1f[3]; float d8D = (d > 0.f) ? sqrt_approx(d) : 0.f;

        float part  = wA * dpA + wB * dpB + wC * dpC + wD * dpD;
        float part8 = wA * d8A + wB * d8B + wC * d8C + wD * d8D;
        part  += __shfl_down_sync(0xffffffffu, part, 2);
        part  += __shfl_down_sync(0xffffffffu, part, 1);
        part8 += __shfl_down_sync(0xffffffffu, part8, 2);
        part8 += __shfl_down_sync(0xffffffffu, part8, 1);
        if (q == 0) { sdB[p] = part; sdB[p + 8] = part8; }

        float colA = wp * dpA + wp8 * d8A;
        float colB = wp * dpB + wp8 * d8B;
        float colC = wp * dpC + wp8 * d8C;
        float colD = wp * dpD + wp8 * d8D;
#pragma unroll
        for (int off = 4; off <= 16; off <<= 1) {
            colA += __shfl_xor_sync(0xffffffffu, colA, off);
            colB += __shfl_xor_sync(0xffffffffu, colB, off);
            colC += __shfl_xor_sync(0xffffffffu, colC, off);
            colD += __shfl_xor_sync(0xffffffffu, colD, off);
        }
        if (lane < 4) {
            *(float2*)&sdB[16 + 2 * lane] = make_float2(colA, colB);
            *(float2*)&sdB[24 + 2 * lane] = make_float2(colC, colD);
        }
    }
    __syncthreads();

    // --- softmax(-dist) * tw, renormalized; emit rel hi/lo (warp 0) ---
    if (tid < 32) {
        float v = sdA[tid] + sdB[tid];
        float m = v;
#pragma unroll
        for (int off = 16; off; off >>= 1)
            m = fminf(m, __shfl_xor_sync(0xffffffffu, m, off));
        float r = __expf(m - v) * selw[tid];
        float s = r;
#pragma unroll
        for (int off = 16; off; off >>= 1)
            s += __shfl_xor_sync(0xffffffffu, s, off);
        float rr = __fdividef(r, s);
        uint32_t bits = __float_as_uint(rr);
        srelh[tid] = (unsigned short)(bits >> 16);
        float rl = rr - __uint_as_float(bits & 0xffff0000u);
        srell[tid] = __bfloat16_as_ushort(__float2bfloat16_rn(rl));
    }
    __syncthreads();

    // --- aggregation: out^T = X^T @ rel via mma; warp w -> dout [32w, 32w+32) ---
    {
        const uint32_t* relh32 = (const uint32_t*)srelh;
        const uint32_t* rell32 = (const uint32_t*)srell;
        const int d0 = wrp * 32;
        const int g = lane >> 3, rin = lane & 7;

        float cacc[2][4];
#pragma unroll
        for (int i = 0; i < 2; ++i)
#pragma unroll
            for (int j = 0; j < 4; ++j) cacc[i][j] = 0.f;

#pragma unroll
        for (int kc = 0; kc < 2; ++kc) {
            uint32_t bh[2], bl[2];
            bh[0] = relh32[kc * 8 + q];
            bh[1] = relh32[kc * 8 + 4 + q];
            bl[0] = rell32[kc * 8 + q];
            bl[1] = rell32[kc * 8 + 4 + q];

#pragma unroll
            for (int mt = 0; mt < 2; ++mt) {
                uint32_t aoff = (uint32_t)(((kc * 16 + (g >> 1) * 8 + rin) * BPITCH
                                            + d0 + mt * 16 + (g & 1) * 8) * 2);
                uint32_t ah[4], al[4];
                ldmatrix_x4_trans(ah, hbase + aoff);
                ldmatrix_x4_trans(al, lbase + aoff);

                mma_bf16(cacc[mt], ah, bh);
                mma_bf16(cacc[mt], ah, bl);
                mma_bf16(cacc[mt], al, bh);
            }
        }

        if (q == 0) {
#pragma unroll
            for (int mt = 0; mt < 2; ++mt) {
                int dd = d0 + mt * 16 + p;
                out[(size_t)node * DOUT + dd]     = cacc[mt][0] + bias[dd];
                out[(size_t)node * DOUT + dd + 8] = cacc[mt][2] + bias[dd + 8];
            }
        }
    }
}

// ---------------------------------------------------------------------------
// Launch (PDL chain: wsplit -> gemm -> node)
// ---------------------------------------------------------------------------
extern "C" void kernel_launch(void* const* d_in, const int* in_sizes, int n_in,
                              void* d_out, int out_size)
{
    const float* feat   = (const float*)d_in[0];
    const float* ew     = (const float*)d_in[1];
    const float* weight = (const float*)d_in[2];
    const float* bias   = (const float*)d_in[3];
    const int*   nbr    = (const int*)  d_in[4];
    float*       out    = (float*)d_out;

    int n = in_sizes[0] / DIN;

    wsplit_kernel<<<64, 256>>>(weight);

    {
        cudaLaunchConfig_t cfg = {};
        cudaLaunchAttribute attr[1];
        attr[0].id = cudaLaunchAttributeProgrammaticStreamSerialization;
        attr[0].val.programmaticStreamSerializationAllowed = 1;
        cfg.gridDim  = dim3((n + 127) / 128, 1, 1);
        cfg.blockDim = dim3(256, 1, 1);
        cfg.attrs    = attr;
        cfg.numAttrs = 1;
        cudaLaunchKernelEx(&cfg, gemm_kernel, feat, n);
    }
    {
        cudaLaunchConfig_t cfg = {};
        cudaLaunchAttribute attr[1];
        attr[0].id = cudaLaunchAttributeProgrammaticStreamSerialization;
        attr[0].val.programmaticStreamSerializationAllowed = 1;
        cfg.gridDim  = dim3(n, 1, 1);
        cfg.blockDim = dim3(128, 1, 1);
        cfg.attrs    = attr;
        cfg.numAttrs = 1;
        cudaLaunchKernelEx(&cfg, node_kernel, ew, nbr, bias, out, n);
    }
}

// round 14
// speedup vs baseline: 1.4235x; 1.4235x over previous
#include <cuda_runtime.h>
#include <cuda_bf16.h>
#include <cstdint>

// Problem constants
#define DIN   128
#define DOUT  128
#define DEG   48
#define KSEL  32
#define NPAD  50048
#define NODES_PER_CTA 4

// Interleaved split storage: per node 256 bf16 = [128 hi][128 lo] (512 B row)
__device__ __nv_bfloat16 g_xs[(size_t)NPAD * 256];
__device__ __nv_bfloat16 g_wThi[128 * 128];            // W^T hi, [n][k]
__device__ __nv_bfloat16 g_wTlo[128 * 128];            // W^T lo, [n][k]

// ---------------------------------------------------------------------------
// Common helpers
// ---------------------------------------------------------------------------
__device__ __forceinline__ uint32_t smem_u32(const void* p) {
    uint32_t a;
    asm("{ .reg .u64 t; cvta.to.shared.u64 t, %1; cvt.u32.u64 %0, t; }" : "=r"(a) : "l"(p));
    return a;
}

__device__ __forceinline__ void ldmatrix_x4(uint32_t* r, uint32_t addr) {
    asm volatile("ldmatrix.sync.aligned.m8n8.x4.shared.b16 {%0,%1,%2,%3}, [%4];"
                 : "=r"(r[0]), "=r"(r[1]), "=r"(r[2]), "=r"(r[3]) : "r"(addr));
}

__device__ __forceinline__ void ldmatrix_x4_trans(uint32_t* r, uint32_t addr) {
    asm volatile("ldmatrix.sync.aligned.m8n8.x4.trans.shared.b16 {%0,%1,%2,%3}, [%4];"
                 : "=r"(r[0]), "=r"(r[1]), "=r"(r[2]), "=r"(r[3]) : "r"(addr));
}

__device__ __forceinline__ void mma_bf16(float* c, const uint32_t* a, const uint32_t* b) {
    asm volatile(
        "mma.sync.aligned.m16n8k16.row.col.f32.bf16.bf16.f32 "
        "{%0,%1,%2,%3}, {%4,%5,%6,%7}, {%8,%9}, {%0,%1,%2,%3};"
        : "+f"(c[0]), "+f"(c[1]), "+f"(c[2]), "+f"(c[3])
        : "r"(a[0]), "r"(a[1]), "r"(a[2]), "r"(a[3]), "r"(b[0]), "r"(b[1]));
}

__device__ __forceinline__ float sqrt_approx(float x) {
    float y;
    asm("sqrt.approx.f32 %0, %1;" : "=f"(y) : "f"(x));
    return y;
}

// Truncation split: hi = top-16 bits of fp32, lo = rn-bf16 of (x - hi).
__device__ __forceinline__ void split4(float4 v, uint2& hp, uint2& lp) {
    uint32_t ax = __float_as_uint(v.x), ay = __float_as_uint(v.y);
    uint32_t az = __float_as_uint(v.z), aw = __float_as_uint(v.w);
    hp.x = __byte_perm(ax, ay, 0x7632);
    hp.y = __byte_perm(az, aw, 0x7632);
    float lx = v.x - __uint_as_float(ax & 0xffff0000u);
    float ly = v.y - __uint_as_float(ay & 0xffff0000u);
    float lz = v.z - __uint_as_float(az & 0xffff0000u);
    float lw = v.w - __uint_as_float(aw & 0xffff0000u);
    asm("cvt.rn.bf16x2.f32 %0, %1, %2;" : "=r"(lp.x) : "f"(ly), "f"(lx));
    asm("cvt.rn.bf16x2.f32 %0, %1, %2;" : "=r"(lp.y) : "f"(lw), "f"(lz));
}

__device__ __forceinline__ void split2(float x, float y, uint32_t& hp, uint32_t& lp) {
    uint32_t ax = __float_as_uint(x), ay = __float_as_uint(y);
    hp = __byte_perm(ax, ay, 0x7632);
    float lx = x - __uint_as_float(ax & 0xffff0000u);
    float ly = y - __uint_as_float(ay & 0xffff0000u);
    asm("cvt.rn.bf16x2.f32 %0, %1, %2;" : "=r"(lp) : "f"(ly), "f"(lx));
}

// ---------------------------------------------------------------------------
// Kernel 0: transpose + split W -> g_wThi/g_wTlo  ([n][k] bf16)
// ---------------------------------------------------------------------------
__global__ __launch_bounds__(256) void wsplit_kernel(const float* __restrict__ W)
{
    int idx = blockIdx.x * 256 + threadIdx.x;
    int k = idx >> 7, nn = idx & 127;
    float v = W[k * 128 + nn];
    uint32_t b = __float_as_uint(v);
    uint32_t hbits = b & 0xffff0000u;
    float lo = v - __uint_as_float(hbits);
    g_wThi[nn * 128 + k] = __ushort_as_bfloat16((unsigned short)(hbits >> 16));
    g_wTlo[nn * 128 + k] = __float2bfloat16_rn(lo);
}

// ---------------------------------------------------------------------------
// Kernel A: x = feat @ W via bf16 3-pass mma.sync; epilogue -> interleaved g_xs
// ---------------------------------------------------------------------------
#define GAP 40   // bf16 smem pitch (80 B), ldmatrix conflict-free

__global__ __launch_bounds__(256) void gemm_kernel(const float* __restrict__ feat,
                                                   int n)
{
    __shared__ __align__(16) __nv_bfloat16 sa_h[128 * GAP];
    __shared__ __align__(16) __nv_bfloat16 sa_l[128 * GAP];
    __shared__ __align__(16) __nv_bfloat16 sb_h[128 * GAP];
    __shared__ __align__(16) __nv_bfloat16 sb_l[128 * GAP];

    const int tid  = threadIdx.x;
    const int lane = tid & 31;
    const int wrp  = tid >> 5;
    const int row0 = blockIdx.x * 128;

    const int m0 = (wrp & 1) * 64;
    const int n0 = (wrp >> 1) * 32;
    const int rsel = lane >> 3, rin = lane & 7;

    const uint32_t sah = smem_u32(sa_h), sal = smem_u32(sa_l);
    const uint32_t sbh = smem_u32(sb_h), sbl = smem_u32(sb_l);

    float acc[4][4][4];
#pragma unroll
    for (int mt = 0; mt < 4; ++mt)
#pragma unroll
        for (int nt = 0; nt < 4; ++nt)
#pragma unroll
            for (int i = 0; i < 4; ++i) acc[mt][nt][i] = 0.0f;

    for (int kt = 0; kt < 4; ++kt) {
#pragma unroll
        for (int i = 0; i < 4; ++i) {
            int idx = tid + i * 256;
            int r = idx >> 3, q = idx & 7;
            int rg = row0 + r; if (rg > n - 1) rg = n - 1;
            float4 v = *(const float4*)&feat[(size_t)rg * DIN + kt * 32 + q * 4];
            uint2 hp, lp;
            split4(v, hp, lp);
            *(uint2*)&sa_h[r * GAP + q * 4] = hp;
            *(uint2*)&sa_l[r * GAP + q * 4] = lp;
        }
#pragma unroll
        for (int i = 0; i < 2; ++i) {
            int idx = tid + i * 256;
            int r = idx >> 2, q = idx & 3;
            *(uint4*)&sb_h[r * GAP + q * 8] =
                *(const uint4*)&g_wThi[r * 128 + kt * 32 + q * 8];
            *(uint4*)&sb_l[r * GAP + q * 8] =
                *(const uint4*)&g_wTlo[r * 128 + kt * 32 + q * 8];
        }
        __syncthreads();

#pragma unroll
        for (int kc = 0; kc < 2; ++kc) {
            const uint32_t kadd = kc * 32;
            uint32_t bh[8], bl[8];
#pragma unroll
            for (int h = 0; h < 2; ++h) {
                uint32_t boff = (uint32_t)((n0 + h * 16 + (rsel >> 1) * 8 + rin) * GAP
                                           + (rsel & 1) * 8) * 2 + kadd;
                ldmatrix_x4(&bh[h * 4], sbh + boff);
                ldmatrix_x4(&bl[h * 4], sbl + boff);
            }
#pragma unroll
            for (int mt = 0; mt < 4; ++mt) {
                uint32_t aoff = (uint32_t)((m0 + mt * 16 + (rsel & 1) * 8 + rin) * GAP
                                           + (rsel >> 1) * 8) * 2 + kadd;
                uint32_t ah[4], al[4];
                ldmatrix_x4(ah, sah + aoff);
                ldmatrix_x4(al, sal + aoff);
#pragma unroll
                for (int nt = 0; nt < 4; ++nt) {
                    mma_bf16(acc[mt][nt], ah, &bh[nt * 2]);
                    mma_bf16(acc[mt][nt], ah, &bl[nt * 2]);
                    mma_bf16(acc[mt][nt], al, &bh[nt * 2]);
                }
            }
        }
        __syncthreads();
    }

    // epilogue: trunc-split, store interleaved [128 hi][128 lo] per node row
#pragma unroll
    for (int mt = 0; mt < 4; ++mt) {
        int ra = row0 + m0 + mt * 16 + (lane >> 2);
#pragma unroll
        for (int nt = 0; nt < 4; ++nt) {
            int cb = n0 + nt * 8 + 2 * (lane & 3);
            uint32_t hp, lp;
            split2(acc[mt][nt][0], acc[mt][nt][1], hp, lp);
            *(uint32_t*)&g_xs[(size_t)ra * 256 + cb]       = hp;
            *(uint32_t*)&g_xs[(size_t)ra * 256 + 128 + cb] = lp;
            split2(acc[mt][nt][2], acc[mt][nt][3], hp, lp);
            *(uint32_t*)&g_xs[(size_t)(ra + 8) * 256 + cb]       = hp;
            *(uint32_t*)&g_xs[(size_t)(ra + 8) * 256 + 128 + cb] = lp;
        }
    }
}

// ---------------------------------------------------------------------------
// Kernel B: 4 nodes per CTA (amortize wave/launch overhead).
// Per node: topk (register rank), cp.async gather, symmetric 3-tile Gram,
// in-fragment dist, fast softmax, X^T mma agg. 128 threads.
// ---------------------------------------------------------------------------
#define BPITCH 136

__global__ __launch_bounds__(128) void node_kernel(const float* __restrict__ ew,
                                                   const int*   __restrict__ nbr,
                                                   const float* __restrict__ bias,
                                                   float*       __restrict__ out,
                                                   int n)
{
    __shared__ __align__(16) __nv_bfloat16 xhi[32 * BPITCH];
    __shared__ __align__(16) __nv_bfloat16 xlo[32 * BPITCH];
    __shared__ float selw[32];
    __shared__ int   selid[32];
    __shared__ float ssq[32];
    __shared__ float sdA[32];
    __shared__ float sdB[32];
    __shared__ __align__(4) unsigned short srelh[32];
    __shared__ __align__(4) unsigned short srell[32];

    const int tid  = threadIdx.x;
    const int lane = tid & 31;
    const int wrp  = tid >> 5;
    const uint32_t hbase = smem_u32(xhi);
    const uint32_t lbase = smem_u32(xlo);
    const int p = lane >> 2;
    const int q = lane & 3;

    for (int it = 0; it < NODES_PER_CTA; ++it) {
        const int node = blockIdx.x * NODES_PER_CTA + it;

        // --- top-32 of 49: rank via uniform vector loads ---
        if (tid < DEG + 1) {
            float v; int myid;
            if (tid < DEG) {
                v    = ew[(size_t)node * DEG + tid];
                myid = nbr[(size_t)node * DEG + tid];
            } else {
                v = 1.0f; myid = node;
            }
            int rank = (1.0f > v) ? 1 : 0;   // self-loop j=48
            const float4* row = (const float4*)(ew + (size_t)node * DEG);
#pragma unroll
            for (int c = 0; c < 12; ++c) {
                float4 w4 = row[c];
                int j0 = c * 4;
                rank += (w4.x > v) || (w4.x == v && (j0 + 0) < tid);
                rank += (w4.y > v) || (w4.y == v && (j0 + 1) < tid);
                rank += (w4.z > v) || (w4.z == v && (j0 + 2) < tid);
                rank += (w4.w > v) || (w4.w == v && (j0 + 3) < tid);
            }
            if (rank < KSEL) { selw[rank] = v; selid[rank] = myid; }
        }
        __syncthreads();

        // --- gather via cp.async: 1 row = 512B = 32 lanes x 16B ---
        {
            const int r0 = wrp * 8;
            const uint32_t dbase = (lane < 16 ? hbase : lbase) + (lane & 15) * 16;
#pragma unroll
            for (int r = 0; r < 8; ++r) {
                const int row = r0 + r;
                const char* src = (const char*)g_xs + (size_t)selid[row] * 512 + lane * 16;
                uint32_t dst = dbase + (uint32_t)(row * (BPITCH * 2));
                asm volatile("cp.async.ca.shared.global [%0], [%1], 16;"
                             :: "r"(dst), "l"(src));
            }
            asm volatile("cp.async.commit_group;");
            asm volatile("cp.async.wait_group 0;");
        }
        __syncthreads();

        // --- Gram, 3 tiles ---
        float c0f[4] = {0.f, 0.f, 0.f, 0.f};
        float c1f[4] = {0.f, 0.f, 0.f, 0.f};

        if (wrp < 2) {
            const int m0 = wrp * 16;
            const int rsel = lane >> 3, rin = lane & 7;
            const uint32_t a_off = (uint32_t)((m0 + (rsel & 1) * 8 + rin) * BPITCH
                                              + (rsel >> 1) * 8) * 2;
#pragma unroll
            for (int kc = 0; kc < 8; ++kc) {
                uint32_t ah[4], al[4];
                ldmatrix_x4(ah, hbase + a_off + kc * 32);
                ldmatrix_x4(al, lbase + a_off + kc * 32);
                uint32_t bh0[2] = {ah[0], ah[2]}, bh1[2] = {ah[1], ah[3]};
                uint32_t bl0[2] = {al[0], al[2]}, bl1[2] = {al[1], al[3]};
                mma_bf16(c0f, ah, bh0); mma_bf16(c0f, ah, bl0); mma_bf16(c0f, al, bh0);
                mma_bf16(c1f, ah, bh1); mma_bf16(c1f, ah, bl1); mma_bf16(c1f, al, bh1);
            }
            if (p == 2 * q)     { ssq[m0 + p] = c0f[0]; ssq[m0 + p + 8] = c1f[2]; }
            if (p == 2 * q + 1) { ssq[m0 + p] = c0f[1]; ssq[m0 + p + 8] = c1f[3]; }
        } else if (wrp == 2) {
            const int rsel = lane >> 3, rin = lane & 7;
            const uint32_t a_off = (uint32_t)(((rsel & 1) * 8 + rin) * BPITCH
                                              + (rsel >> 1) * 8) * 2;
            const uint32_t b_off = (uint32_t)((16 + (rsel >> 1) * 8 + rin) * BPITCH
                                              + (rsel & 1) * 8) * 2;
#pragma unroll
            for (int kc = 0; kc < 8; ++kc) {
                uint32_t ah[4], al[4], bh[4], bl[4];
                ldmatrix_x4(ah, hbase + a_off + kc * 32);
                ldmatrix_x4(al, lbase + a_off + kc * 32);
                ldmatrix_x4(bh, hbase + b_off + kc * 32);
                ldmatrix_x4(bl, lbase + b_off + kc * 32);
                mma_bf16(c0f, ah, &bh[0]); mma_bf16(c0f, ah, &bl[0]); mma_bf16(c0f, al, &bh[0]);
                mma_bf16(c1f, ah, &bh[2]); mma_bf16(c1f, ah, &bl[2]); mma_bf16(c1f, al, &bh[2]);
            }
        }
        __syncthreads();   // ssq visible to all

        // --- dist partials ---
        if (wrp < 2) {
            const int m0 = wrp * 16;
            const int b0 = m0 + 2 * q, b1 = b0 + 1, b2 = b0 + 8, b3 = b2 + 1;
            const float w0 = selw[b0], w1 = selw[b1], w2 = selw[b2], w3 = selw[b3];
            const float s0 = ssq[b0], s1 = ssq[b1], s2 = ssq[b2], s3 = ssq[b3];
            const float sqa  = ssq[m0 + p];
            const float sqa8 = ssq[m0 + p + 8];

            float d, part = 0.f, part8 = 0.f;
            d = sqa  + s0 - 2.f * c0f[0]; part  = fmaf(w0, (d > 0.f) ? sqrt_approx(d) : 0.f, part);
            d = sqa  + s1 - 2.f * c0f[1]; part  = fmaf(w1, (d > 0.f) ? sqrt_approx(d) : 0.f, part);
            d = sqa  + s2 - 2.f * c1f[0]; part  = fmaf(w2, (d > 0.f) ? sqrt_approx(d) : 0.f, part);
            d = sqa  + s3 - 2.f * c1f[1]; part  = fmaf(w3, (d > 0.f) ? sqrt_approx(d) : 0.f, part);
            d = sqa8 + s0 - 2.f * c0f[2]; part8 = fmaf(w0, (d > 0.f) ? sqrt_approx(d) : 0.f, part8);
            d = sqa8 + s1 - 2.f * c0f[3]; part8 = fmaf(w1, (d > 0.f) ? sqrt_approx(d) : 0.f, part8);
            d = sqa8 + s2 - 2.f * c1f[2]; part8 = fmaf(w2, (d > 0.f) ? sqrt_approx(d) : 0.f, part8);
            d = sqa8 + s3 - 2.f * c1f[3]; part8 = fmaf(w3, (d > 0.f) ? sqrt_approx(d) : 0.f, part8);

            part  += __shfl_down_sync(0xffffffffu, part, 2);
            part  += __shfl_down_sync(0xffffffffu, part, 1);
            part8 += __shfl_down_sync(0xffffffffu, part8, 2);
            part8 += __shfl_down_sync(0xffffffffu, part8, 1);
            if (q == 0) { sdA[m0 + p] = part; sdA[m0 + p + 8] = part8; }
        } else if (wrp == 2) {
            const int cA = 16 + 2 * q, cB = cA + 1, cC = cA + 8, cD = cC + 1;
            const float wA = selw[cA], wB = selw[cB], wC = selw[cC], wD = selw[cD];
            const float sA = ssq[cA], sB = ssq[cB], sC = ssq[cC], sD = ssq[cD];
            const float sqa  = ssq[p];
            const float sqa8 = ssq[p + 8];
            const float wp   = selw[p];
            const float wp8  = selw[p + 8];

            float d;
            d = sqa  + sA - 2.f * c0f[0]; float dpA = (d > 0.f) ? sqrt_approx(d) : 0.f;
            d = sqa  + sB - 2.f * c0f[1]; float dpB = (d > 0.f) ? sqrt_approx(d) : 0.f;
            d = sqa  + sC - 2.f * c1f[0]; float dpC = (d > 0.f) ? sqrt_approx(d) : 0.f;
            d = sqa  + sD - 2.f * c1f[1]; float dpD = (d > 0.f) ? sqrt_approx(d) : 0.f;
            d = sqa8 + sA - 2.f * c0f[2]; float d8A = (d > 0.f) ? sqrt_approx(d) : 0.f;
            d = sqa8 + sB - 2.f * c0f[3]; float d8B = (d > 0.f) ? sqrt_approx(d) : 0.f;
            d = sqa8 + sC - 2.f * c1f[2]; float d8C = (d > 0.f) ? sqrt_approx(d) : 0.f;
            d = sqa8 + sD - 2.f * c1f[3]; float d8D = (d > 0.f) ? sqrt_approx(d) : 0.f;

            float part  = wA * dpA + wB * dpB + wC * dpC + wD * dpD;
            float part8 = wA * d8A + wB * d8B + wC * d8C + wD * d8D;
            part  += __shfl_down_sync(0xffffffffu, part, 2);
            part  += __shfl_down_sync(0xffffffffu, part, 1);
            part8 += __shfl_down_sync(0xffffffffu, part8, 2);
            part8 += __shfl_down_sync(0xffffffffu, part8, 1);
            if (q == 0) { sdB[p] = part; sdB[p + 8] = part8; }

            float colA = wp * dpA + wp8 * d8A;
            float colB = wp * dpB + wp8 * d8B;
            float colC = wp * dpC + wp8 * d8C;
            float colD = wp * dpD + wp8 * d8D;
#pragma unroll
            for (int off = 4; off <= 16; off <<= 1) {
                colA += __shfl_xor_sync(0xffffffffu, colA, off);
                colB += __shfl_xor_sync(0xffffffffu, colB, off);
                colC += __shfl_xor_sync(0xffffffffu, colC, off);
                colD += __shfl_xor_sync(0xffffffffu, colD, off);
            }
            if (lane < 4) {
                *(float2*)&sdB[16 + 2 * lane] = make_float2(colA, colB);
                *(float2*)&sdB[24 + 2 * lane] = make_float2(colC, colD);
            }
        }
        __syncthreads();

        // --- softmax(-dist) * tw, renormalized; emit rel hi/lo (warp 0) ---
        if (tid < 32) {
            float v = sdA[tid] + sdB[tid];
            float m = v;
#pragma unroll
            for (int off = 16; off; off >>= 1)
                m = fminf(m, __shfl_xor_sync(0xffffffffu, m, off));
            float r = __expf(m - v) * selw[tid];
            float s = r;
#pragma unroll
            for (int off = 16; off; off >>= 1)
                s += __shfl_xor_sync(0xffffffffu, s, off);
            float rr = __fdividef(r, s);
            uint32_t bits = __float_as_uint(rr);
            srelh[tid] = (unsigned short)(bits >> 16);
            float rl = rr - __uint_as_float(bits & 0xffff0000u);
            srell[tid] = __bfloat16_as_ushort(__float2bfloat16_rn(rl));
        }
        __syncthreads();

        // --- aggregation: out^T = X^T @ rel; warp w -> dout [32w, 32w+32) ---
        {
            const uint32_t* relh32 = (const uint32_t*)srelh;
            const uint32_t* rell32 = (const uint32_t*)srell;
            const int d0 = wrp * 32;
            const int g = lane >> 3, rin = lane & 7;

            float cacc[2][4];
#pragma unroll
            for (int i = 0; i < 2; ++i)
#pragma unroll
                for (int j = 0; j < 4; ++j) cacc[i][j] = 0.f;

#pragma unroll
            for (int kc = 0; kc < 2; ++kc) {
                uint32_t bh[2], bl[2];
                bh[0] = relh32[kc * 8 + q];
                bh[1] = relh32[kc * 8 + 4 + q];
                bl[0] = rell32[kc * 8 + q];
                bl[1] = rell32[kc * 8 + 4 + q];

#pragma unroll
                for (int mt = 0; mt < 2; ++mt) {
                    uint32_t aoff = (uint32_t)(((kc * 16 + (g >> 1) * 8 + rin) * BPITCH
                                                + d0 + mt * 16 + (g & 1) * 8) * 2);
                    uint32_t ah[4], al[4];
                    ldmatrix_x4_trans(ah, hbase + aoff);
                    ldmatrix_x4_trans(al, lbase + aoff);

                    mma_bf16(cacc[mt], ah, bh);
                    mma_bf16(cacc[mt], ah, bl);
                    mma_bf16(cacc[mt], al, bh);
                }
            }

            if (q == 0) {
#pragma unroll
                for (int mt = 0; mt < 2; ++mt) {
                    int dd = d0 + mt * 16 + p;
                    out[(size_t)node * DOUT + dd]     = cacc[mt][0] + bias[dd];
                    out[(size_t)node * DOUT + dd + 8] = cacc[mt][2] + bias[dd + 8];
                }
            }
        }
        __syncthreads();   // protect selw/selid/xhi/xlo reuse next iteration
    }
}

// ---------------------------------------------------------------------------
// Launch
// ---------------------------------------------------------------------------
extern "C" void kernel_launch(void* const* d_in, const int* in_sizes, int n_in,
                              void* d_out, int out_size)
{
    const float* feat   = (const float*)d_in[0];
    const float* ew     = (const float*)d_in[1];
    const float* weight = (const float*)d_in[2];
    const float* bias   = (const float*)d_in[3];
    const int*   nbr    = (const int*)  d_in[4];
    float*       out    = (float*)d_out;

    int n = in_sizes[0] / DIN;   // 50000, divisible by NODES_PER_CTA

    wsplit_kernel<<<64, 256>>>(weight);
    gemm_kernel<<<(n + 127) / 128, 256>>>(feat, n);
    node_kernel<<<n / NODES_PER_CTA, 128>>>(ew, nbr, bias, out, n);
}

// round 15
// speedup vs baseline: 1.4735x; 1.0352x over previous
#include <cuda_runtime.h>
#include <cuda_bf16.h>
#include <cstdint>

// Problem constants
#define DIN   128
#define DOUT  128
#define DEG   48
#define KSEL  32
#define NPAD  50048

// Interleaved split storage: per node 256 bf16 = [128 hi][128 lo] (512 B row)
__device__ __nv_bfloat16 g_xs[(size_t)NPAD * 256];

// ---------------------------------------------------------------------------
// Common helpers
// ---------------------------------------------------------------------------
__device__ __forceinline__ uint32_t smem_u32(const void* p) {
    uint32_t a;
    asm("{ .reg .u64 t; cvta.to.shared.u64 t, %1; cvt.u32.u64 %0, t; }" : "=r"(a) : "l"(p));
    return a;
}

__device__ __forceinline__ void ldmatrix_x4(uint32_t* r, uint32_t addr) {
    asm volatile("ldmatrix.sync.aligned.m8n8.x4.shared.b16 {%0,%1,%2,%3}, [%4];"
                 : "=r"(r[0]), "=r"(r[1]), "=r"(r[2]), "=r"(r[3]) : "r"(addr));
}

__device__ __forceinline__ void ldmatrix_x4_trans(uint32_t* r, uint32_t addr) {
    asm volatile("ldmatrix.sync.aligned.m8n8.x4.trans.shared.b16 {%0,%1,%2,%3}, [%4];"
                 : "=r"(r[0]), "=r"(r[1]), "=r"(r[2]), "=r"(r[3]) : "r"(addr));
}

__device__ __forceinline__ void mma_bf16(float* c, const uint32_t* a, const uint32_t* b) {
    asm volatile(
        "mma.sync.aligned.m16n8k16.row.col.f32.bf16.bf16.f32 "
        "{%0,%1,%2,%3}, {%4,%5,%6,%7}, {%8,%9}, {%0,%1,%2,%3};"
        : "+f"(c[0]), "+f"(c[1]), "+f"(c[2]), "+f"(c[3])
        : "r"(a[0]), "r"(a[1]), "r"(a[2]), "r"(a[3]), "r"(b[0]), "r"(b[1]));
}

__device__ __forceinline__ float sqrt_approx(float x) {
    float y;
    asm("sqrt.approx.f32 %0, %1;" : "=f"(y) : "f"(x));
    return y;
}

// Truncation split: hi = top-16 bits of fp32, lo = rn-bf16 of (x - hi).
__device__ __forceinline__ void split4(float4 v, uint2& hp, uint2& lp) {
    uint32_t ax = __float_as_uint(v.x), ay = __float_as_uint(v.y);
    uint32_t az = __float_as_uint(v.z), aw = __float_as_uint(v.w);
    hp.x = __byte_perm(ax, ay, 0x7632);
    hp.y = __byte_perm(az, aw, 0x7632);
    float lx = v.x - __uint_as_float(ax & 0xffff0000u);
    float ly = v.y - __uint_as_float(ay & 0xffff0000u);
    float lz = v.z - __uint_as_float(az & 0xffff0000u);
    float lw = v.w - __uint_as_float(aw & 0xffff0000u);
    asm("cvt.rn.bf16x2.f32 %0, %1, %2;" : "=r"(lp.x) : "f"(ly), "f"(lx));
    asm("cvt.rn.bf16x2.f32 %0, %1, %2;" : "=r"(lp.y) : "f"(lw), "f"(lz));
}

__device__ __forceinline__ void split2(float x, float y, uint32_t& hp, uint32_t& lp) {
    uint32_t ax = __float_as_uint(x), ay = __float_as_uint(y);
    hp = __byte_perm(ax, ay, 0x7632);
    float lx = x - __uint_as_float(ax & 0xffff0000u);
    float ly = y - __uint_as_float(ay & 0xffff0000u);
    asm("cvt.rn.bf16x2.f32 %0, %1, %2;" : "=r"(lp) : "f"(ly), "f"(lx));
}

// ---------------------------------------------------------------------------
// Kernel A: x = feat @ W via bf16 3-pass mma.sync.
// W split on the fly; B tile stored K-major [k][n], b-frags via trans ldmatrix
// (bit-identical fragments to the old pre-transposed path). Epilogue -> g_xs.
// ---------------------------------------------------------------------------
#define GAP    40   // A-tile bf16 pitch (80 B), ldmatrix conflict-free
#define WPITCH 136  // B-tile bf16 pitch (272 B), trans-ldmatrix conflict-free

__global__ __launch_bounds__(256) void gemm_kernel(const float* __restrict__ feat,
                                                   const float* __restrict__ W,
                                                   int n)
{
    __shared__ __align__(16) __nv_bfloat16 sa_h[128 * GAP];
    __shared__ __align__(16) __nv_bfloat16 sa_l[128 * GAP];
    __shared__ __align__(16) __nv_bfloat16 sb_h[32 * WPITCH];
    __shared__ __align__(16) __nv_bfloat16 sb_l[32 * WPITCH];

    const int tid  = threadIdx.x;
    const int lane = tid & 31;
    const int wrp  = tid >> 5;
    const int row0 = blockIdx.x * 128;

    const int m0 = (wrp & 1) * 64;
    const int n0 = (wrp >> 1) * 32;
    const int rsel = lane >> 3, rin = lane & 7;

    const uint32_t sah = smem_u32(sa_h), sal = smem_u32(sa_l);
    const uint32_t sbh = smem_u32(sb_h), sbl = smem_u32(sb_l);

    float acc[4][4][4];
#pragma unroll
    for (int mt = 0; mt < 4; ++mt)
#pragma unroll
        for (int nt = 0; nt < 4; ++nt)
#pragma unroll
            for (int i = 0; i < 4; ++i) acc[mt][nt][i] = 0.0f;

    for (int kt = 0; kt < 4; ++kt) {
        // A chunk: feat[row0..row0+128)[kt*32..+32), split to bf16 hi/lo
#pragma unroll
        for (int i = 0; i < 4; ++i) {
            int idx = tid + i * 256;
            int r = idx >> 3, q = idx & 7;
            int rg = row0 + r; if (rg > n - 1) rg = n - 1;
            float4 v = *(const float4*)&feat[(size_t)rg * DIN + kt * 32 + q * 4];
            uint2 hp, lp;
            split4(v, hp, lp);
            *(uint2*)&sa_h[r * GAP + q * 4] = hp;
            *(uint2*)&sa_l[r * GAP + q * 4] = lp;
        }
        // B chunk: W[kt*32..+32)[0..128) fp32, split on the fly, K-major store
#pragma unroll
        for (int i = 0; i < 4; ++i) {
            int idx = tid + i * 256;               // 0..1023
            int r = idx >> 5, q = idx & 31;        // k-row 0..31, float4 col
            float4 v = *(const float4*)&W[(size_t)(kt * 32 + r) * 128 + q * 4];
            uint2 hp, lp;
            split4(v, hp, lp);
            *(uint2*)&sb_h[r * WPITCH + q * 4] = hp;
            *(uint2*)&sb_l[r * WPITCH + q * 4] = lp;
        }
        __syncthreads();

#pragma unroll
        for (int kc = 0; kc < 2; ++kc) {
            uint32_t bh[8], bl[8];
#pragma unroll
            for (int h = 0; h < 2; ++h) {
                // trans ldmatrix from [k][n]: blocks (k0-7,n0-7),(k8-15,n0-7),
                // (k0-7,n8-15),(k8-15,n8-15) == validated non-trans [n][k] order
                uint32_t boff = (uint32_t)((kc * 16 + (rsel & 1) * 8 + rin) * WPITCH
                                           + n0 + h * 16 + (rsel >> 1) * 8) * 2;
                ldmatrix_x4_trans(&bh[h * 4], sbh + boff);
                ldmatrix_x4_trans(&bl[h * 4], sbl + boff);
            }
#pragma unroll
            for (int mt = 0; mt < 4; ++mt) {
                uint32_t aoff = (uint32_t)((m0 + mt * 16 + (rsel & 1) * 8 + rin) * GAP
                                           + (rsel >> 1) * 8) * 2 + kc * 32;
                uint32_t ah[4], al[4];
                ldmatrix_x4(ah, sah + aoff);
                ldmatrix_x4(al, sal + aoff);
#pragma unroll
                for (int nt = 0; nt < 4; ++nt) {
                    mma_bf16(acc[mt][nt], ah, &bh[nt * 2]);
                    mma_bf16(acc[mt][nt], ah, &bl[nt * 2]);
                    mma_bf16(acc[mt][nt], al, &bh[nt * 2]);
                }
            }
        }
        __syncthreads();
    }

    // epilogue: trunc-split, store interleaved [128 hi][128 lo] per node row
#pragma unroll
    for (int mt = 0; mt < 4; ++mt) {
        int ra = row0 + m0 + mt * 16 + (lane >> 2);
#pragma unroll
        for (int nt = 0; nt < 4; ++nt) {
            int cb = n0 + nt * 8 + 2 * (lane & 3);
            uint32_t hp, lp;
            split2(acc[mt][nt][0], acc[mt][nt][1], hp, lp);
            *(uint32_t*)&g_xs[(size_t)ra * 256 + cb]       = hp;
            *(uint32_t*)&g_xs[(size_t)ra * 256 + 128 + cb] = lp;
            split2(acc[mt][nt][2], acc[mt][nt][3], hp, lp);
            *(uint32_t*)&g_xs[(size_t)(ra + 8) * 256 + cb]       = hp;
            *(uint32_t*)&g_xs[(size_t)(ra + 8) * 256 + 128 + cb] = lp;
        }
    }
}

// ---------------------------------------------------------------------------
// Kernel B: topk (register rank), cp.async gather, symmetric 3-tile Gram,
//           in-fragment dist, fast softmax, X^T mma agg. 1 CTA/node, 128 thr.
// ---------------------------------------------------------------------------
#define BPITCH 136

__global__ __launch_bounds__(128) void node_kernel(const float* __restrict__ ew,
                                                   const int*   __restrict__ nbr,
                                                   const float* __restrict__ bias,
                                                   float*       __restrict__ out,
                                                   int n)
{
    __shared__ __align__(16) __nv_bfloat16 xhi[32 * BPITCH];
    __shared__ __align__(16) __nv_bfloat16 xlo[32 * BPITCH];
    __shared__ float selw[32];
    __shared__ int   selid[32];
    __shared__ float ssq[32];
    __shared__ float sdA[32];
    __shared__ float sdB[32];
    __shared__ __align__(4) unsigned short srelh[32];
    __shared__ __align__(4) unsigned short srell[32];

    const int node = blockIdx.x;
    const int tid  = threadIdx.x;
    const int lane = tid & 31;
    const int wrp  = tid >> 5;

    // --- top-32 of 49: rank via uniform vector loads, no smem staging ---
    if (tid < DEG + 1) {
        float v; int myid;
        if (tid < DEG) {
            v    = ew[(size_t)node * DEG + tid];
            myid = nbr[(size_t)node * DEG + tid];
        } else {
            v = 1.0f; myid = node;
        }
        int rank = (1.0f > v) ? 1 : 0;   // self-loop j=48: j<tid never for tid<=48
        const float4* row = (const float4*)(ew + (size_t)node * DEG);
#pragma unroll
        for (int c = 0; c < 12; ++c) {
            float4 w4 = row[c];
            int j0 = c * 4;
            rank += (w4.x > v) || (w4.x == v && (j0 + 0) < tid);
            rank += (w4.y > v) || (w4.y == v && (j0 + 1) < tid);
            rank += (w4.z > v) || (w4.z == v && (j0 + 2) < tid);
            rank += (w4.w > v) || (w4.w == v && (j0 + 3) < tid);
        }
        if (rank < KSEL) { selw[rank] = v; selid[rank] = myid; }
    }
    __syncthreads();

    // --- gather via cp.async: 1 row = 512B = 32 lanes x 16B ---
    {
        const int r0 = wrp * 8;
        const uint32_t hbase0 = smem_u32(xhi);
        const uint32_t lbase0 = smem_u32(xlo);
        const uint32_t dbase  = (lane < 16 ? hbase0 : lbase0) + (lane & 15) * 16;
#pragma unroll
        for (int r = 0; r < 8; ++r) {
            const int row = r0 + r;
            const char* src = (const char*)g_xs + (size_t)selid[row] * 512 + lane * 16;
            uint32_t dst = dbase + (uint32_t)(row * (BPITCH * 2));
            asm volatile("cp.async.ca.shared.global [%0], [%1], 16;"
                         :: "r"(dst), "l"(src));
        }
        asm volatile("cp.async.commit_group;");
        asm volatile("cp.async.wait_group 0;");
    }
    __syncthreads();

    // --- Gram, 3 tiles: w0 diag(0,0) A=B aliased, w1 diag(16,16), w2 offdiag ---
    const uint32_t hbase = smem_u32(xhi);
    const uint32_t lbase = smem_u32(xlo);
    const int p = lane >> 2;
    const int q = lane & 3;
    float c0f[4] = {0.f, 0.f, 0.f, 0.f};
    float c1f[4] = {0.f, 0.f, 0.f, 0.f};

    if (wrp < 2) {
        const int m0 = wrp * 16;
        const int rsel = lane >> 3, rin = lane & 7;
        const uint32_t a_off = (uint32_t)((m0 + (rsel & 1) * 8 + rin) * BPITCH
                                          + (rsel >> 1) * 8) * 2;
#pragma unroll
        for (int kc = 0; kc < 8; ++kc) {
            uint32_t ah[4], al[4];
            ldmatrix_x4(ah, hbase + a_off + kc * 32);
            ldmatrix_x4(al, lbase + a_off + kc * 32);
            uint32_t bh0[2] = {ah[0], ah[2]}, bh1[2] = {ah[1], ah[3]};
            uint32_t bl0[2] = {al[0], al[2]}, bl1[2] = {al[1], al[3]};
            mma_bf16(c0f, ah, bh0); mma_bf16(c0f, ah, bl0); mma_bf16(c0f, al, bh0);
            mma_bf16(c1f, ah, bh1); mma_bf16(c1f, ah, bl1); mma_bf16(c1f, al, bh1);
        }
        if (p == 2 * q)     { ssq[m0 + p] = c0f[0]; ssq[m0 + p + 8] = c1f[2]; }
        if (p == 2 * q + 1) { ssq[m0 + p] = c0f[1]; ssq[m0 + p + 8] = c1f[3]; }
    } else if (wrp == 2) {
        const int rsel = lane >> 3, rin = lane & 7;
        const uint32_t a_off = (uint32_t)(((rsel & 1) * 8 + rin) * BPITCH
                                          + (rsel >> 1) * 8) * 2;
        const uint32_t b_off = (uint32_t)((16 + (rsel >> 1) * 8 + rin) * BPITCH
                                          + (rsel & 1) * 8) * 2;
#pragma unroll
        for (int kc = 0; kc < 8; ++kc) {
            uint32_t ah[4], al[4], bh[4], bl[4];
            ldmatrix_x4(ah, hbase + a_off + kc * 32);
            ldmatrix_x4(al, lbase + a_off + kc * 32);
            ldmatrix_x4(bh, hbase + b_off + kc * 32);
            ldmatrix_x4(bl, lbase + b_off + kc * 32);
            mma_bf16(c0f, ah, &bh[0]); mma_bf16(c0f, ah, &bl[0]); mma_bf16(c0f, al, &bh[0]);
            mma_bf16(c1f, ah, &bh[2]); mma_bf16(c1f, ah, &bl[2]); mma_bf16(c1f, al, &bh[2]);
        }
    }
    __syncthreads();   // ssq visible to all

    // --- dist partials ---
    if (wrp < 2) {
        const int m0 = wrp * 16;
        const int b0 = m0 + 2 * q, b1 = b0 + 1, b2 = b0 + 8, b3 = b2 + 1;
        const float w0 = selw[b0], w1 = selw[b1], w2 = selw[b2], w3 = selw[b3];
        const float s0 = ssq[b0], s1 = ssq[b1], s2 = ssq[b2], s3 = ssq[b3];
        const float sqa  = ssq[m0 + p];
        const float sqa8 = ssq[m0 + p + 8];

        float d, part = 0.f, part8 = 0.f;
        d = sqa  + s0 - 2.f * c0f[0]; part  = fmaf(w0, (d > 0.f) ? sqrt_approx(d) : 0.f, part);
        d = sqa  + s1 - 2.f * c0f[1]; part  = fmaf(w1, (d > 0.f) ? sqrt_approx(d) : 0.f, part);
        d = sqa  + s2 - 2.f * c1f[0]; part  = fmaf(w2, (d > 0.f) ? sqrt_approx(d) : 0.f, part);
        d = sqa  + s3 - 2.f * c1f[1]; part  = fmaf(w3, (d > 0.f) ? sqrt_approx(d) : 0.f, part);
        d = sqa8 + s0 - 2.f * c0f[2]; part8 = fmaf(w0, (d > 0.f) ? sqrt_approx(d) : 0.f, part8);
        d = sqa8 + s1 - 2.f * c0f[3]; part8 = fmaf(w1, (d > 0.f) ? sqrt_approx(d) : 0.f, part8);
        d = sqa8 + s2 - 2.f * c1f[2]; part8 = fmaf(w2, (d > 0.f) ? sqrt_approx(d) : 0.f, part8);
        d = sqa8 + s3 - 2.f * c1f[3]; part8 = fmaf(w3, (d > 0.f) ? sqrt_approx(d) : 0.f, part8);

        part  += __shfl_down_sync(0xffffffffu, part, 2);
        part  += __shfl_down_sync(0xffffffffu, part, 1);
        part8 += __shfl_down_sync(0xffffffffu, part8, 2);
        part8 += __shfl_down_sync(0xffffffffu, part8, 1);
        if (q == 0) { sdA[m0 + p] = part; sdA[m0 + p + 8] = part8; }
    } else if (wrp == 2) {
        const int cA = 16 + 2 * q, cB = cA + 1, cC = cA + 8, cD = cC + 1;
        const float wA = selw[cA], wB = selw[cB], wC = selw[cC], wD = selw[cD];
        const float sA = ssq[cA], sB = ssq[cB], sC = ssq[cC], sD = ssq[cD];
        const float sqa  = ssq[p];
        const float sqa8 = ssq[p + 8];
        const float wp   = selw[p];
        const float wp8  = selw[p + 8];

        float d;
        d = sqa  + sA - 2.f * c0f[0]; float dpA = (d > 0.f) ? sqrt_approx(d) : 0.f;
        d = sqa  + sB - 2.f * c0f[1]; float dpB = (d > 0.f) ? sqrt_approx(d) : 0.f;
        d = sqa  + sC - 2.f * c1f[0]; float dpC = (d > 0.f) ? sqrt_approx(d) : 0.f;
        d = sqa  + sD - 2.f * c1f[1]; float dpD = (d > 0.f) ? sqrt_approx(d) : 0.f;
        d = sqa8 + sA - 2.f * c0f[2]; float d8A = (d > 0.f) ? sqrt_approx(d) : 0.f;
        d = sqa8 + sB - 2.f * c0f[3]; float d8B = (d > 0.f) ? sqrt_approx(d) : 0.f;
        d = sqa8 + sC - 2.f * c1f[2]; float d8C = (d > 0.f) ? sqrt_approx(d) : 0.f;
        d = sqa8 + sD - 2.f * c1f[3]; float d8D = (d > 0.f) ? sqrt_approx(d) : 0.f;

        float part  = wA * dpA + wB * dpB + wC * dpC + wD * dpD;
        float part8 = wA * d8A + wB * d8B + wC * d8C + wD * d8D;
        part  += __shfl_down_sync(0xffffffffu, part, 2);
        part  += __shfl_down_sync(0xffffffffu, part, 1);
        part8 += __shfl_down_sync(0xffffffffu, part8, 2);
        part8 += __shfl_down_sync(0xffffffffu, part8, 1);
        if (q == 0) { sdB[p] = part; sdB[p + 8] = part8; }

        float colA = wp * dpA + wp8 * d8A;
        float colB = wp * dpB + wp8 * d8B;
        float colC = wp * dpC + wp8 * d8C;
        float colD = wp * dpD + wp8 * d8D;
#pragma unroll
        for (int off = 4; off <= 16; off <<= 1) {
            colA += __shfl_xor_sync(0xffffffffu, colA, off);
            colB += __shfl_xor_sync(0xffffffffu, colB, off);
            colC += __shfl_xor_sync(0xffffffffu, colC, off);
            colD += __shfl_xor_sync(0xffffffffu, colD, off);
        }
        if (lane < 4) {
            *(float2*)&sdB[16 + 2 * lane] = make_float2(colA, colB);
            *(float2*)&sdB[24 + 2 * lane] = make_float2(colC, colD);
        }
    }
    __syncthreads();

    // --- softmax(-dist) * tw, renormalized; emit rel hi/lo (warp 0) ---
    if (tid < 32) {
        float v = sdA[tid] + sdB[tid];
        float m = v;
#pragma unroll
        for (int off = 16; off; off >>= 1)
            m = fminf(m, __shfl_xor_sync(0xffffffffu, m, off));
        float r = __expf(m - v) * selw[tid];
        float s = r;
#pragma unroll
        for (int off = 16; off; off >>= 1)
            s += __shfl_xor_sync(0xffffffffu, s, off);
        float rr = __fdividef(r, s);
        uint32_t bits = __float_as_uint(rr);
        srelh[tid] = (unsigned short)(bits >> 16);
        float rl = rr - __uint_as_float(bits & 0xffff0000u);
        srell[tid] = __bfloat16_as_ushort(__float2bfloat16_rn(rl));
    }
    __syncthreads();

    // --- aggregation: out^T = X^T @ rel via mma; warp w -> dout [32w, 32w+32) ---
    {
        const uint32_t* relh32 = (const uint32_t*)srelh;
        const uint32_t* rell32 = (const uint32_t*)srell;
        const int d0 = wrp * 32;
        const int g = lane >> 3, rin = lane & 7;

        float cacc[2][4];
#pragma unroll
        for (int i = 0; i < 2; ++i)
#pragma unroll
            for (int j = 0; j < 4; ++j) cacc[i][j] = 0.f;

#pragma unroll
        for (int kc = 0; kc < 2; ++kc) {
            uint32_t bh[2], bl[2];
            bh[0] = relh32[kc * 8 + q];
            bh[1] = relh32[kc * 8 + 4 + q];
            bl[0] = rell32[kc * 8 + q];
            bl[1] = rell32[kc * 8 + 4 + q];

#pragma unroll
            for (int mt = 0; mt < 2; ++mt) {
                uint32_t aoff = (uint32_t)(((kc * 16 + (g >> 1) * 8 + rin) * BPITCH
                                            + d0 + mt * 16 + (g & 1) * 8) * 2);
                uint32_t ah[4], al[4];
                ldmatrix_x4_trans(ah, hbase + aoff);
                ldmatrix_x4_trans(al, lbase + aoff);

                mma_bf16(cacc[mt], ah, bh);
                mma_bf16(cacc[mt], ah, bl);
                mma_bf16(cacc[mt], al, bh);
            }
        }

        if (q == 0) {
#pragma unroll
            for (int mt = 0; mt < 2; ++mt) {
                int dd = d0 + mt * 16 + p;
                out[(size_t)node * DOUT + dd]     = cacc[mt][0] + bias[dd];
                out[(size_t)node * DOUT + dd + 8] = cacc[mt][2] + bias[dd + 8];
            }
        }
    }
}

// ---------------------------------------------------------------------------
// Launch (2-kernel chain; wsplit folded into gemm)
// ---------------------------------------------------------------------------
extern "C" void kernel_launch(void* const* d_in, const int* in_sizes, int n_in,
                              void* d_out, int out_size)
{
    const float* feat   = (const float*)d_in[0];
    const float* ew     = (const float*)d_in[1];
    const float* weight = (const float*)d_in[2];
    const float* bias   = (const float*)d_in[3];
    const int*   nbr    = (const int*)  d_in[4];
    float*       out    = (float*)d_out;

    int n = in_sizes[0] / DIN;

    gemm_kernel<<<(n + 127) / 128, 256>>>(feat, weight, n);
    node_kernel<<<n, 128>>>(ew, nbr, bias, out, n);
}

// round 16
// speedup vs baseline: 1.5195x; 1.0312x over previous
#include <cuda_runtime.h>
#include <cuda_bf16.h>
#include <cstdint>

// Problem constants
#define DIN   128
#define DOUT  128
#define DEG   48
#define KSEL  32
#define NPAD  50048

// Interleaved split storage: per node 256 bf16 = [128 hi][128 lo] (512 B row)
__device__ __nv_bfloat16 g_xs[(size_t)NPAD * 256];

// ---------------------------------------------------------------------------
// Common helpers
// ---------------------------------------------------------------------------
__device__ __forceinline__ uint32_t smem_u32(const void* p) {
    uint32_t a;
    asm("{ .reg .u64 t; cvta.to.shared.u64 t, %1; cvt.u32.u64 %0, t; }" : "=r"(a) : "l"(p));
    return a;
}

__device__ __forceinline__ void ldmatrix_x4(uint32_t* r, uint32_t addr) {
    asm volatile("ldmatrix.sync.aligned.m8n8.x4.shared.b16 {%0,%1,%2,%3}, [%4];"
                 : "=r"(r[0]), "=r"(r[1]), "=r"(r[2]), "=r"(r[3]) : "r"(addr));
}

__device__ __forceinline__ void ldmatrix_x4_trans(uint32_t* r, uint32_t addr) {
    asm volatile("ldmatrix.sync.aligned.m8n8.x4.trans.shared.b16 {%0,%1,%2,%3}, [%4];"
                 : "=r"(r[0]), "=r"(r[1]), "=r"(r[2]), "=r"(r[3]) : "r"(addr));
}

__device__ __forceinline__ void mma_bf16(float* c, const uint32_t* a, const uint32_t* b) {
    asm volatile(
        "mma.sync.aligned.m16n8k16.row.col.f32.bf16.bf16.f32 "
        "{%0,%1,%2,%3}, {%4,%5,%6,%7}, {%8,%9}, {%0,%1,%2,%3};"
        : "+f"(c[0]), "+f"(c[1]), "+f"(c[2]), "+f"(c[3])
        : "r"(a[0]), "r"(a[1]), "r"(a[2]), "r"(a[3]), "r"(b[0]), "r"(b[1]));
}

__device__ __forceinline__ float sqrt_approx(float x) {
    float y;
    asm("sqrt.approx.f32 %0, %1;" : "=f"(y) : "f"(x));
    return y;
}

// Truncation split: hi = top-16 bits of fp32, lo = rn-bf16 of (x - hi).
__device__ __forceinline__ void split4(float4 v, uint2& hp, uint2& lp) {
    uint32_t ax = __float_as_uint(v.x), ay = __float_as_uint(v.y);
    uint32_t az = __float_as_uint(v.z), aw = __float_as_uint(v.w);
    hp.x = __byte_perm(ax, ay, 0x7632);
    hp.y = __byte_perm(az, aw, 0x7632);
    float lx = v.x - __uint_as_float(ax & 0xffff0000u);
    float ly = v.y - __uint_as_float(ay & 0xffff0000u);
    float lz = v.z - __uint_as_float(az & 0xffff0000u);
    float lw = v.w - __uint_as_float(aw & 0xffff0000u);
    asm("cvt.rn.bf16x2.f32 %0, %1, %2;" : "=r"(lp.x) : "f"(ly), "f"(lx));
    asm("cvt.rn.bf16x2.f32 %0, %1, %2;" : "=r"(lp.y) : "f"(lw), "f"(lz));
}

__device__ __forceinline__ void split2(float x, float y, uint32_t& hp, uint32_t& lp) {
    uint32_t ax = __float_as_uint(x), ay = __float_as_uint(y);
    hp = __byte_perm(ax, ay, 0x7632);
    float lx = x - __uint_as_float(ax & 0xffff0000u);
    float ly = y - __uint_as_float(ay & 0xffff0000u);
    asm("cvt.rn.bf16x2.f32 %0, %1, %2;" : "=r"(lp) : "f"(ly), "f"(lx));
}

// ---------------------------------------------------------------------------
// Kernel A: x = feat @ W via bf16 3-pass mma.sync, register-prefetch pipeline.
// W split on the fly; B tile K-major [k][n], b-frags via trans ldmatrix.
// Epilogue -> interleaved g_xs.
// ---------------------------------------------------------------------------
#define GAP    40   // A-tile bf16 pitch (80 B), ldmatrix conflict-free
#define WPITCH 136  // B-tile bf16 pitch (272 B), trans-ldmatrix conflict-free

__global__ __launch_bounds__(256) void gemm_kernel(const float* __restrict__ feat,
                                                   const float* __restrict__ W,
                                                   int n)
{
    __shared__ __align__(16) __nv_bfloat16 sa_h[128 * GAP];
    __shared__ __align__(16) __nv_bfloat16 sa_l[128 * GAP];
    __shared__ __align__(16) __nv_bfloat16 sb_h[32 * WPITCH];
    __shared__ __align__(16) __nv_bfloat16 sb_l[32 * WPITCH];

    const int tid  = threadIdx.x;
    const int lane = tid & 31;
    const int wrp  = tid >> 5;
    const int row0 = blockIdx.x * 128;

    const int m0 = (wrp & 1) * 64;
    const int n0 = (wrp >> 1) * 32;
    const int rsel = lane >> 3, rin = lane & 7;

    const uint32_t sah = smem_u32(sa_h), sal = smem_u32(sa_l);
    const uint32_t sbh = smem_u32(sb_h), sbl = smem_u32(sb_l);

    // Per-thread load coordinates (invariant over kt)
    int ar[4], aq[4], wr[4], wq[4];
#pragma unroll
    for (int i = 0; i < 4; ++i) {
        int idx = tid + i * 256;
        int r = idx >> 3;
        aq[i] = idx & 7;
        int rg = row0 + r; if (rg > n - 1) rg = n - 1;
        ar[i] = rg;
        wr[i] = idx >> 5;
        wq[i] = idx & 31;
    }

    float acc[4][4][4];
#pragma unroll
    for (int mt = 0; mt < 4; ++mt)
#pragma unroll
        for (int nt = 0; nt < 4; ++nt)
#pragma unroll
            for (int i = 0; i < 4; ++i) acc[mt][nt][i] = 0.0f;

    // Prefetch kt = 0
    float4 pa[4], pw[4];
#pragma unroll
    for (int i = 0; i < 4; ++i) {
        pa[i] = *(const float4*)&feat[(size_t)ar[i] * DIN + aq[i] * 4];
        pw[i] = *(const float4*)&W[(size_t)wr[i] * 128 + wq[i] * 4];
    }

    for (int kt = 0; kt < 4; ++kt) {
        // split + store current chunk (from registers)
#pragma unroll
        for (int i = 0; i < 4; ++i) {
            int idx = tid + i * 256;
            int r = idx >> 3;
            uint2 hp, lp;
            split4(pa[i], hp, lp);
            *(uint2*)&sa_h[r * GAP + aq[i] * 4] = hp;
            *(uint2*)&sa_l[r * GAP + aq[i] * 4] = lp;
        }
#pragma unroll
        for (int i = 0; i < 4; ++i) {
            uint2 hp, lp;
            split4(pw[i], hp, lp);
            *(uint2*)&sb_h[wr[i] * WPITCH + wq[i] * 4] = hp;
            *(uint2*)&sb_l[wr[i] * WPITCH + wq[i] * 4] = lp;
        }
        __syncthreads();

        // Issue prefetch for kt+1 BEFORE the mma block: LDG latency overlaps mma
        if (kt < 3) {
            const int kn = (kt + 1) * 32;
#pragma unroll
            for (int i = 0; i < 4; ++i) {
                pa[i] = *(const float4*)&feat[(size_t)ar[i] * DIN + kn + aq[i] * 4];
                pw[i] = *(const float4*)&W[(size_t)(kn + wr[i]) * 128 + wq[i] * 4];
            }
        }

#pragma unroll
        for (int kc = 0; kc < 2; ++kc) {
            uint32_t bh[8], bl[8];
#pragma unroll
            for (int h = 0; h < 2; ++h) {
                // trans ldmatrix from [k][n]: blocks (k0-7,n0-7),(k8-15,n0-7),
                // (k0-7,n8-15),(k8-15,n8-15) == validated non-trans [n][k] order
                uint32_t boff = (uint32_t)((kc * 16 + (rsel & 1) * 8 + rin) * WPITCH
                                           + n0 + h * 16 + (rsel >> 1) * 8) * 2;
                ldmatrix_x4_trans(&bh[h * 4], sbh + boff);
                ldmatrix_x4_trans(&bl[h * 4], sbl + boff);
            }
#pragma unroll
            for (int mt = 0; mt < 4; ++mt) {
                uint32_t aoff = (uint32_t)((m0 + mt * 16 + (rsel & 1) * 8 + rin) * GAP
                                           + (rsel >> 1) * 8) * 2 + kc * 32;
                uint32_t ah[4], al[4];
                ldmatrix_x4(ah, sah + aoff);
                ldmatrix_x4(al, sal + aoff);
#pragma unroll
                for (int nt = 0; nt < 4; ++nt) {
                    mma_bf16(acc[mt][nt], ah, &bh[nt * 2]);
                    mma_bf16(acc[mt][nt], ah, &bl[nt * 2]);
                    mma_bf16(acc[mt][nt], al, &bh[nt * 2]);
                }
            }
        }
        __syncthreads();
    }

    // epilogue: trunc-split, store interleaved [128 hi][128 lo] per node row
#pragma unroll
    for (int mt = 0; mt < 4; ++mt) {
        int ra = row0 + m0 + mt * 16 + (lane >> 2);
#pragma unroll
        for (int nt = 0; nt < 4; ++nt) {
            int cb = n0 + nt * 8 + 2 * (lane & 3);
            uint32_t hp, lp;
            split2(acc[mt][nt][0], acc[mt][nt][1], hp, lp);
            *(uint32_t*)&g_xs[(size_t)ra * 256 + cb]       = hp;
            *(uint32_t*)&g_xs[(size_t)ra * 256 + 128 + cb] = lp;
            split2(acc[mt][nt][2], acc[mt][nt][3], hp, lp);
            *(uint32_t*)&g_xs[(size_t)(ra + 8) * 256 + cb]       = hp;
            *(uint32_t*)&g_xs[(size_t)(ra + 8) * 256 + 128 + cb] = lp;
        }
    }
}

// ---------------------------------------------------------------------------
// Kernel B: topk (register rank), cp.async gather, symmetric 3-tile Gram,
//           in-fragment dist, fast softmax, X^T mma agg. 1 CTA/node, 128 thr.
//           (unchanged from R15 best)
// ---------------------------------------------------------------------------
#define BPITCH 136

__global__ __launch_bounds__(128) void node_kernel(const float* __restrict__ ew,
                                                   const int*   __restrict__ nbr,
                                                   const float* __restrict__ bias,
                                                   float*       __restrict__ out,
                                                   int n)
{
    __shared__ __align__(16) __nv_bfloat16 xhi[32 * BPITCH];
    __shared__ __align__(16) __nv_bfloat16 xlo[32 * BPITCH];
    __shared__ float selw[32];
    __shared__ int   selid[32];
    __shared__ float ssq[32];
    __shared__ float sdA[32];
    __shared__ float sdB[32];
    __shared__ __align__(4) unsigned short srelh[32];
    __shared__ __align__(4) unsigned short srell[32];

    const int node = blockIdx.x;
    const int tid  = threadIdx.x;
    const int lane = tid & 31;
    const int wrp  = tid >> 5;

    // --- top-32 of 49: rank via uniform vector loads, no smem staging ---
    if (tid < DEG + 1) {
        float v; int myid;
        if (tid < DEG) {
            v    = ew[(size_t)node * DEG + tid];
            myid = nbr[(size_t)node * DEG + tid];
        } else {
            v = 1.0f; myid = node;
        }
        int rank = (1.0f > v) ? 1 : 0;   // self-loop j=48: j<tid never for tid<=48
        const float4* row = (const float4*)(ew + (size_t)node * DEG);
#pragma unroll
        for (int c = 0; c < 12; ++c) {
            float4 w4 = row[c];
            int j0 = c * 4;
            rank += (w4.x > v) || (w4.x == v && (j0 + 0) < tid);
            rank += (w4.y > v) || (w4.y == v && (j0 + 1) < tid);
            rank += (w4.z > v) || (w4.z == v && (j0 + 2) < tid);
            rank += (w4.w > v) || (w4.w == v && (j0 + 3) < tid);
        }
        if (rank < KSEL) { selw[rank] = v; selid[rank] = myid; }
    }
    __syncthreads();

    // --- gather via cp.async: 1 row = 512B = 32 lanes x 16B ---
    {
        const int r0 = wrp * 8;
        const uint32_t hbase0 = smem_u32(xhi);
        const uint32_t lbase0 = smem_u32(xlo);
        const uint32_t dbase  = (lane < 16 ? hbase0 : lbase0) + (lane & 15) * 16;
#pragma unroll
        for (int r = 0; r < 8; ++r) {
            const int row = r0 + r;
            const char* src = (const char*)g_xs + (size_t)selid[row] * 512 + lane * 16;
            uint32_t dst = dbase + (uint32_t)(row * (BPITCH * 2));
            asm volatile("cp.async.ca.shared.global [%0], [%1], 16;"
                         :: "r"(dst), "l"(src));
        }
        asm volatile("cp.async.commit_group;");
        asm volatile("cp.async.wait_group 0;");
    }
    __syncthreads();

    // --- Gram, 3 tiles: w0 diag(0,0) A=B aliased, w1 diag(16,16), w2 offdiag ---
    const uint32_t hbase = smem_u32(xhi);
    const uint32_t lbase = smem_u32(xlo);
    const int p = lane >> 2;
    const int q = lane & 3;
    float c0f[4] = {0.f, 0.f, 0.f, 0.f};
    float c1f[4] = {0.f, 0.f, 0.f, 0.f};

    if (wrp < 2) {
        const int m0 = wrp * 16;
        const int rsel = lane >> 3, rin = lane & 7;
        const uint32_t a_off = (uint32_t)((m0 + (rsel & 1) * 8 + rin) * BPITCH
                                          + (rsel >> 1) * 8) * 2;
#pragma unroll
        for (int kc = 0; kc < 8; ++kc) {
            uint32_t ah[4], al[4];
            ldmatrix_x4(ah, hbase + a_off + kc * 32);
            ldmatrix_x4(al, lbase + a_off + kc * 32);
            uint32_t bh0[2] = {ah[0], ah[2]}, bh1[2] = {ah[1], ah[3]};
            uint32_t bl0[2] = {al[0], al[2]}, bl1[2] = {al[1], al[3]};
            mma_bf16(c0f, ah, bh0); mma_bf16(c0f, ah, bl0); mma_bf16(c0f, al, bh0);
            mma_bf16(c1f, ah, bh1); mma_bf16(c1f, ah, bl1); mma_bf16(c1f, al, bh1);
        }
        if (p == 2 * q)     { ssq[m0 + p] = c0f[0]; ssq[m0 + p + 8] = c1f[2]; }
        if (p == 2 * q + 1) { ssq[m0 + p] = c0f[1]; ssq[m0 + p + 8] = c1f[3]; }
    } else if (wrp == 2) {
        const int rsel = lane >> 3, rin = lane & 7;
        const uint32_t a_off = (uint32_t)(((rsel & 1) * 8 + rin) * BPITCH
                                          + (rsel >> 1) * 8) * 2;
        const uint32_t b_off = (uint32_t)((16 + (rsel >> 1) * 8 + rin) * BPITCH
                                          + (rsel & 1) * 8) * 2;
#pragma unroll
        for (int kc = 0; kc < 8; ++kc) {
            uint32_t ah[4], al[4], bh[4], bl[4];
            ldmatrix_x4(ah, hbase + a_off + kc * 32);
            ldmatrix_x4(al, lbase + a_off + kc * 32);
            ldmatrix_x4(bh, hbase + b_off + kc * 32);
            ldmatrix_x4(bl, lbase + b_off + kc * 32);
            mma_bf16(c0f, ah, &bh[0]); mma_bf16(c0f, ah, &bl[0]); mma_bf16(c0f, al, &bh[0]);
            mma_bf16(c1f, ah, &bh[2]); mma_bf16(c1f, ah, &bl[2]); mma_bf16(c1f, al, &bh[2]);
        }
    }
    __syncthreads();   // ssq visible to all

    // --- dist partials ---
    if (wrp < 2) {
        const int m0 = wrp * 16;
        const int b0 = m0 + 2 * q, b1 = b0 + 1, b2 = b0 + 8, b3 = b2 + 1;
        const float w0 = selw[b0], w1 = selw[b1], w2 = selw[b2], w3 = selw[b3];
        const float s0 = ssq[b0], s1 = ssq[b1], s2 = ssq[b2], s3 = ssq[b3];
        const float sqa  = ssq[m0 + p];
        const float sqa8 = ssq[m0 + p + 8];

        float d, part = 0.f, part8 = 0.f;
        d = sqa  + s0 - 2.f * c0f[0]; part  = fmaf(w0, (d > 0.f) ? sqrt_approx(d) : 0.f, part);
        d = sqa  + s1 - 2.f * c0f[1]; part  = fmaf(w1, (d > 0.f) ? sqrt_approx(d) : 0.f, part);
        d = sqa  + s2 - 2.f * c1f[0]; part  = fmaf(w2, (d > 0.f) ? sqrt_approx(d) : 0.f, part);
        d = sqa  + s3 - 2.f * c1f[1]; part  = fmaf(w3, (d > 0.f) ? sqrt_approx(d) : 0.f, part);
        d = sqa8 + s0 - 2.f * c0f[2]; part8 = fmaf(w0, (d > 0.f) ? sqrt_approx(d) : 0.f, part8);
        d = sqa8 + s1 - 2.f * c0f[3]; part8 = fmaf(w1, (d > 0.f) ? sqrt_approx(d) : 0.f, part8);
        d = sqa8 + s2 - 2.f * c1f[2]; part8 = fmaf(w2, (d > 0.f) ? sqrt_approx(d) : 0.f, part8);
        d = sqa8 + s3 - 2.f * c1f[3]; part8 = fmaf(w3, (d > 0.f) ? sqrt_approx(d) : 0.f, part8);

        part  += __shfl_down_sync(0xffffffffu, part, 2);
        part  += __shfl_down_sync(0xffffffffu, part, 1);
        part8 += __shfl_down_sync(0xffffffffu, part8, 2);
        part8 += __shfl_down_sync(0xffffffffu, part8, 1);
        if (q == 0) { sdA[m0 + p] = part; sdA[m0 + p + 8] = part8; }
    } else if (wrp == 2) {
        const int cA = 16 + 2 * q, cB = cA + 1, cC = cA + 8, cD = cC + 1;
        const float wA = selw[cA], wB = selw[cB], wC = selw[cC], wD = selw[cD];
        const float sA = ssq[cA], sB = ssq[cB], sC = ssq[cC], sD = ssq[cD];
        const float sqa  = ssq[p];
        const float sqa8 = ssq[p + 8];
        const float wp   = selw[p];
        const float wp8  = selw[p + 8];

        float d;
        d = sqa  + sA - 2.f * c0f[0]; float dpA = (d > 0.f) ? sqrt_approx(d) : 0.f;
        d = sqa  + sB - 2.f * c0f[1]; float dpB = (d > 0.f) ? sqrt_approx(d) : 0.f;
        d = sqa  + sC - 2.f * c1f[0]; float dpC = (d > 0.f) ? sqrt_approx(d) : 0.f;
        d = sqa  + sD - 2.f * c1f[1]; float dpD = (d > 0.f) ? sqrt_approx(d) : 0.f;
        d = sqa8 + sA - 2.f * c0f[2]; float d8A = (d > 0.f) ? sqrt_approx(d) : 0.f;
        d = sqa8 + sB - 2.f * c0f[3]; float d8B = (d > 0.f) ? sqrt_approx(d) : 0.f;
        d = sqa8 + sC - 2.f * c1f[2]; float d8C = (d > 0.f) ? sqrt_approx(d) : 0.f;
        d = sqa8 + sD - 2.f * c1f[3]; float d8D = (d > 0.f) ? sqrt_approx(d) : 0.f;

        float part  = wA * dpA + wB * dpB + wC * dpC + wD * dpD;
        float part8 = wA * d8A + wB * d8B + wC * d8C + wD * d8D;
        part  += __shfl_down_sync(0xffffffffu, part, 2);
        part  += __shfl_down_sync(0xffffffffu, part, 1);
        part8 += __shfl_down_sync(0xffffffffu, part8, 2);
        part8 += __shfl_down_sync(0xffffffffu, part8, 1);
        if (q == 0) { sdB[p] = part; sdB[p + 8] = part8; }

        float colA = wp * dpA + wp8 * d8A;
        float colB = wp * dpB + wp8 * d8B;
        float colC = wp * dpC + wp8 * d8C;
        float colD = wp * dpD + wp8 * d8D;
#pragma unroll
        for (int off = 4; off <= 16; off <<= 1) {
            colA += __shfl_xor_sync(0xffffffffu, colA, off);
            colB += __shfl_xor_sync(0xffffffffu, colB, off);
            colC += __shfl_xor_sync(0xffffffffu, colC, off);
            colD += __shfl_xor_sync(0xffffffffu, colD, off);
        }
        if (lane < 4) {
            *(float2*)&sdB[16 + 2 * lane] = make_float2(colA, colB);
            *(float2*)&sdB[24 + 2 * lane] = make_float2(colC, colD);
        }
    }
    __syncthreads();

    // --- softmax(-dist) * tw, renormalized; emit rel hi/lo (warp 0) ---
    if (tid < 32) {
        float v = sdA[tid] + sdB[tid];
        float m = v;
#pragma unroll
        for (int off = 16; off; off >>= 1)
            m = fminf(m, __shfl_xor_sync(0xffffffffu, m, off));
        float r = __expf(m - v) * selw[tid];
        float s = r;
#pragma unroll
        for (int off = 16; off; off >>= 1)
            s += __shfl_xor_sync(0xffffffffu, s, off);
        float rr = __fdividef(r, s);
        uint32_t bits = __float_as_uint(rr);
        srelh[tid] = (unsigned short)(bits >> 16);
        float rl = rr - __uint_as_float(bits & 0xffff0000u);
        srell[tid] = __bfloat16_as_ushort(__float2bfloat16_rn(rl));
    }
    __syncthreads();

    // --- aggregation: out^T = X^T @ rel via mma; warp w -> dout [32w, 32w+32) ---
    {
        const uint32_t* relh32 = (const uint32_t*)srelh;
        const uint32_t* rell32 = (const uint32_t*)srell;
        const int d0 = wrp * 32;
        const int g = lane >> 3, rin = lane & 7;

        float cacc[2][4];
#pragma unroll
        for (int i = 0; i < 2; ++i)
#pragma unroll
            for (int j = 0; j < 4; ++j) cacc[i][j] = 0.f;

#pragma unroll
        for (int kc = 0; kc < 2; ++kc) {
            uint32_t bh[2], bl[2];
            bh[0] = relh32[kc * 8 + q];
            bh[1] = relh32[kc * 8 + 4 + q];
            bl[0] = rell32[kc * 8 + q];
            bl[1] = rell32[kc * 8 + 4 + q];

#pragma unroll
            for (int mt = 0; mt < 2; ++mt) {
                uint32_t aoff = (uint32_t)(((kc * 16 + (g >> 1) * 8 + rin) * BPITCH
                                            + d0 + mt * 16 + (g & 1) * 8) * 2);
                uint32_t ah[4], al[4];
                ldmatrix_x4_trans(ah, hbase + aoff);
                ldmatrix_x4_trans(al, lbase + aoff);

                mma_bf16(cacc[mt], ah, bh);
                mma_bf16(cacc[mt], ah, bl);
                mma_bf16(cacc[mt], al, bh);
            }
        }

        if (q == 0) {
#pragma unroll
            for (int mt = 0; mt < 2; ++mt) {
                int dd = d0 + mt * 16 + p;
                out[(size_t)node * DOUT + dd]     = cacc[mt][0] + bias[dd];
                out[(size_t)node * DOUT + dd + 8] = cacc[mt][2] + bias[dd + 8];
            }
        }
    }
}

// ---------------------------------------------------------------------------
// Launch (2-kernel chain)
// ---------------------------------------------------------------------------
extern "C" void kernel_launch(void* const* d_in, const int* in_sizes, int n_in,
                              void* d_out, int out_size)
{
    const float* feat   = (const float*)d_in[0];
    const float* ew     = (const float*)d_in[1];
    const float* weight = (const float*)d_in[2];
    const float* bias   = (const float*)d_in[3];
    const int*   nbr    = (const int*)  d_in[4];
    float*       out    = (float*)d_out;

    int n = in_sizes[0] / DIN;

    gemm_kernel<<<(n + 127) / 128, 256>>>(feat, weight, n);
    node_kernel<<<n, 128>>>(ew, nbr, bias, out, n);
}

// round 17
// speedup vs baseline: 1.5618x; 1.0278x over previous
#include <cuda_runtime.h>
#include <cuda_bf16.h>
#include <cstdint>

// Problem constants
#define DIN   128
#define DOUT  128
#define DEG   48
#define KSEL  32
#define NPAD  50048

// Interleaved split storage: per node 256 bf16 = [128 hi][128 lo] (512 B row)
__device__ __nv_bfloat16 g_xs[(size_t)NPAD * 256];

// ---------------------------------------------------------------------------
// Common helpers
// ---------------------------------------------------------------------------
__device__ __forceinline__ uint32_t smem_u32(const void* p) {
    uint32_t a;
    asm("{ .reg .u64 t; cvta.to.shared.u64 t, %1; cvt.u32.u64 %0, t; }" : "=r"(a) : "l"(p));
    return a;
}

__device__ __forceinline__ void ldmatrix_x4(uint32_t* r, uint32_t addr) {
    asm volatile("ldmatrix.sync.aligned.m8n8.x4.shared.b16 {%0,%1,%2,%3}, [%4];"
                 : "=r"(r[0]), "=r"(r[1]), "=r"(r[2]), "=r"(r[3]) : "r"(addr));
}

__device__ __forceinline__ void ldmatrix_x4_trans(uint32_t* r, uint32_t addr) {
    asm volatile("ldmatrix.sync.aligned.m8n8.x4.trans.shared.b16 {%0,%1,%2,%3}, [%4];"
                 : "=r"(r[0]), "=r"(r[1]), "=r"(r[2]), "=r"(r[3]) : "r"(addr));
}

__device__ __forceinline__ void mma_bf16(float* c, const uint32_t* a, const uint32_t* b) {
    asm volatile(
        "mma.sync.aligned.m16n8k16.row.col.f32.bf16.bf16.f32 "
        "{%0,%1,%2,%3}, {%4,%5,%6,%7}, {%8,%9}, {%0,%1,%2,%3};"
        : "+f"(c[0]), "+f"(c[1]), "+f"(c[2]), "+f"(c[3])
        : "r"(a[0]), "r"(a[1]), "r"(a[2]), "r"(a[3]), "r"(b[0]), "r"(b[1]));
}

__device__ __forceinline__ float sqrt_approx(float x) {
    float y;
    asm("sqrt.approx.f32 %0, %1;" : "=f"(y) : "f"(x));
    return y;
}

// Truncation split: hi = top-16 bits of fp32, lo = rn-bf16 of (x - hi).
__device__ __forceinline__ void split4(float4 v, uint2& hp, uint2& lp) {
    uint32_t ax = __float_as_uint(v.x), ay = __float_as_uint(v.y);
    uint32_t az = __float_as_uint(v.z), aw = __float_as_uint(v.w);
    hp.x = __byte_perm(ax, ay, 0x7632);
    hp.y = __byte_perm(az, aw, 0x7632);
    float lx = v.x - __uint_as_float(ax & 0xffff0000u);
    float ly = v.y - __uint_as_float(ay & 0xffff0000u);
    float lz = v.z - __uint_as_float(az & 0xffff0000u);
    float lw = v.w - __uint_as_float(aw & 0xffff0000u);
    asm("cvt.rn.bf16x2.f32 %0, %1, %2;" : "=r"(lp.x) : "f"(ly), "f"(lx));
    asm("cvt.rn.bf16x2.f32 %0, %1, %2;" : "=r"(lp.y) : "f"(lw), "f"(lz));
}

__device__ __forceinline__ void split2(float x, float y, uint32_t& hp, uint32_t& lp) {
    uint32_t ax = __float_as_uint(x), ay = __float_as_uint(y);
    hp = __byte_perm(ax, ay, 0x7632);
    float lx = x - __uint_as_float(ax & 0xffff0000u);
    float ly = y - __uint_as_float(ay & 0xffff0000u);
    asm("cvt.rn.bf16x2.f32 %0, %1, %2;" : "=r"(lp) : "f"(ly), "f"(lx));
}

// ---------------------------------------------------------------------------
// Kernel A: x = feat @ W via bf16 3-pass mma.sync, register-prefetch pipeline,
// SMEM-STAGED COALESCED EPILOGUE. B tile K-major [k][n], trans-ldmatrix b-frags.
// ---------------------------------------------------------------------------
#define GAP     40    // A-tile bf16 pitch (80 B), ldmatrix conflict-free
#define WPITCH  136   // B-tile bf16 pitch (272 B), trans-ldmatrix conflict-free
#define SPITCH  264   // stage bf16 pitch (528 B): conflict-free STS + LDS

#define OFF_SAH 0
#define OFF_SAL 10240
#define OFF_SBH 20480
#define OFF_SBL 29184
#define OFF_STG 20480   // stage overlays dead sb area (needs 32*528=16896 <= 17408)
#define GEMM_SMEM 37888

__global__ __launch_bounds__(256) void gemm_kernel(const float* __restrict__ feat,
                                                   const float* __restrict__ W,
                                                   int n)
{
    __shared__ __align__(16) char smem_raw[GEMM_SMEM];
    __nv_bfloat16* sa_hp = (__nv_bfloat16*)(smem_raw + OFF_SAH);
    __nv_bfloat16* sa_lp = (__nv_bfloat16*)(smem_raw + OFF_SAL);
    __nv_bfloat16* sb_hp = (__nv_bfloat16*)(smem_raw + OFF_SBH);
    __nv_bfloat16* sb_lp = (__nv_bfloat16*)(smem_raw + OFF_SBL);
    __nv_bfloat16* stage = (__nv_bfloat16*)(smem_raw + OFF_STG);

    const int tid  = threadIdx.x;
    const int lane = tid & 31;
    const int wrp  = tid >> 5;
    const int row0 = blockIdx.x * 128;

    const int m0 = (wrp & 1) * 64;
    const int n0 = (wrp >> 1) * 32;
    const int rsel = lane >> 3, rin = lane & 7;

    const uint32_t sah = smem_u32(sa_hp), sal = smem_u32(sa_lp);
    const uint32_t sbh = smem_u32(sb_hp), sbl = smem_u32(sb_lp);

    // Per-thread load coordinates (invariant over kt)
    int ar[4], aq[4], wr[4], wq[4];
#pragma unroll
    for (int i = 0; i < 4; ++i) {
        int idx = tid + i * 256;
        int r = idx >> 3;
        aq[i] = idx & 7;
        int rg = row0 + r; if (rg > n - 1) rg = n - 1;
        ar[i] = rg;
        wr[i] = idx >> 5;
        wq[i] = idx & 31;
    }

    float acc[4][4][4];
#pragma unroll
    for (int mt = 0; mt < 4; ++mt)
#pragma unroll
        for (int nt = 0; nt < 4; ++nt)
#pragma unroll
            for (int i = 0; i < 4; ++i) acc[mt][nt][i] = 0.0f;

    // Prefetch kt = 0
    float4 pa[4], pw[4];
#pragma unroll
    for (int i = 0; i < 4; ++i) {
        pa[i] = *(const float4*)&feat[(size_t)ar[i] * DIN + aq[i] * 4];
        pw[i] = *(const float4*)&W[(size_t)wr[i] * 128 + wq[i] * 4];
    }

    for (int kt = 0; kt < 4; ++kt) {
#pragma unroll
        for (int i = 0; i < 4; ++i) {
            int idx = tid + i * 256;
            int r = idx >> 3;
            uint2 hp, lp;
            split4(pa[i], hp, lp);
            *(uint2*)&sa_hp[r * GAP + aq[i] * 4] = hp;
            *(uint2*)&sa_lp[r * GAP + aq[i] * 4] = lp;
        }
#pragma unroll
        for (int i = 0; i < 4; ++i) {
            uint2 hp, lp;
            split4(pw[i], hp, lp);
            *(uint2*)&sb_hp[wr[i] * WPITCH + wq[i] * 4] = hp;
            *(uint2*)&sb_lp[wr[i] * WPITCH + wq[i] * 4] = lp;
        }
        __syncthreads();

        // Prefetch kt+1 before mma: LDG latency overlaps compute
        if (kt < 3) {
            const int kn = (kt + 1) * 32;
#pragma unroll
            for (int i = 0; i < 4; ++i) {
                pa[i] = *(const float4*)&feat[(size_t)ar[i] * DIN + kn + aq[i] * 4];
                pw[i] = *(const float4*)&W[(size_t)(kn + wr[i]) * 128 + wq[i] * 4];
            }
        }

#pragma unroll
        for (int kc = 0; kc < 2; ++kc) {
            uint32_t bh[8], bl[8];
#pragma unroll
            for (int h = 0; h < 2; ++h) {
                uint32_t boff = (uint32_t)((kc * 16 + (rsel & 1) * 8 + rin) * WPITCH
                                           + n0 + h * 16 + (rsel >> 1) * 8) * 2;
                ldmatrix_x4_trans(&bh[h * 4], sbh + boff);
                ldmatrix_x4_trans(&bl[h * 4], sbl + boff);
            }
#pragma unroll
            for (int mt = 0; mt < 4; ++mt) {
                uint32_t aoff = (uint32_t)((m0 + mt * 16 + (rsel & 1) * 8 + rin) * GAP
                                           + (rsel >> 1) * 8) * 2 + kc * 32;
                uint32_t ah[4], al[4];
                ldmatrix_x4(ah, sah + aoff);
                ldmatrix_x4(al, sal + aoff);
#pragma unroll
                for (int nt = 0; nt < 4; ++nt) {
                    mma_bf16(acc[mt][nt], ah, &bh[nt * 2]);
                    mma_bf16(acc[mt][nt], ah, &bl[nt * 2]);
                    mma_bf16(acc[mt][nt], al, &bh[nt * 2]);
                }
            }
        }
        __syncthreads();
    }

    // ----- staged epilogue: frag -> smem (conflict-free) -> coalesced STG.128 -----
    const int p2 = lane >> 2;
    const int cbq = 2 * (lane & 3);
    const int srb = (wrp & 1) * 16;     // stage row group for this warp's m0

#pragma unroll
    for (int mt = 0; mt < 4; ++mt) {
        // scatter this mt's frags into stage[32][SPITCH]
#pragma unroll
        for (int nt = 0; nt < 4; ++nt) {
            int cb = n0 + nt * 8 + cbq;
            uint32_t hp, lp;
            split2(acc[mt][nt][0], acc[mt][nt][1], hp, lp);
            *(uint32_t*)&stage[(srb + p2) * SPITCH + cb]       = hp;
            *(uint32_t*)&stage[(srb + p2) * SPITCH + 128 + cb] = lp;
            split2(acc[mt][nt][2], acc[mt][nt][3], hp, lp);
            *(uint32_t*)&stage[(srb + p2 + 8) * SPITCH + cb]       = hp;
            *(uint32_t*)&stage[(srb + p2 + 8) * SPITCH + 128 + cb] = lp;
        }
        __syncthreads();

        // coalesced copy: 32 rows x 512 B  (1024 uint4, 4 per thread)
#pragma unroll
        for (int i = 0; i < 4; ++i) {
            int idx = tid + i * 256;
            int sr  = idx >> 5;
            int off = idx & 31;
            int gr  = row0 + (sr >> 4) * 64 + mt * 16 + (sr & 15);
            uint4 v = *(const uint4*)&stage[sr * SPITCH + off * 8];
            *(uint4*)((char*)g_xs + (size_t)gr * 512 + off * 16) = v;
        }
        __syncthreads();   // stage reuse next mt
    }
}

// ---------------------------------------------------------------------------
// Kernel B: topk (register rank), cp.async gather, symmetric 3-tile Gram,
//           in-fragment dist, fast softmax, X^T mma agg. 1 CTA/node, 128 thr.
//           (unchanged — R15/R16 best)
// ---------------------------------------------------------------------------
#define BPITCH 136

__global__ __launch_bounds__(128) void node_kernel(const float* __restrict__ ew,
                                                   const int*   __restrict__ nbr,
                                                   const float* __restrict__ bias,
                                                   float*       __restrict__ out,
                                                   int n)
{
    __shared__ __align__(16) __nv_bfloat16 xhi[32 * BPITCH];
    __shared__ __align__(16) __nv_bfloat16 xlo[32 * BPITCH];
    __shared__ float selw[32];
    __shared__ int   selid[32];
    __shared__ float ssq[32];
    __shared__ float sdA[32];
    __shared__ float sdB[32];
    __shared__ __align__(4) unsigned short srelh[32];
    __shared__ __align__(4) unsigned short srell[32];

    const int node = blockIdx.x;
    const int tid  = threadIdx.x;
    const int lane = tid & 31;
    const int wrp  = tid >> 5;

    // --- top-32 of 49: rank via uniform vector loads, no smem staging ---
    if (tid < DEG + 1) {
        float v; int myid;
        if (tid < DEG) {
            v    = ew[(size_t)node * DEG + tid];
            myid = nbr[(size_t)node * DEG + tid];
        } else {
            v = 1.0f; myid = node;
        }
        int rank = (1.0f > v) ? 1 : 0;   // self-loop j=48: j<tid never for tid<=48
        const float4* row = (const float4*)(ew + (size_t)node * DEG);
#pragma unroll
        for (int c = 0; c < 12; ++c) {
            float4 w4 = row[c];
            int j0 = c * 4;
            rank += (w4.x > v) || (w4.x == v && (j0 + 0) < tid);
            rank += (w4.y > v) || (w4.y == v && (j0 + 1) < tid);
            rank += (w4.z > v) || (w4.z == v && (j0 + 2) < tid);
            rank += (w4.w > v) || (w4.w == v && (j0 + 3) < tid);
        }
        if (rank < KSEL) { selw[rank] = v; selid[rank] = myid; }
    }
    __syncthreads();

    // --- gather via cp.async: 1 row = 512B = 32 lanes x 16B ---
    {
        const int r0 = wrp * 8;
        const uint32_t hbase0 = smem_u32(xhi);
        const uint32_t lbase0 = smem_u32(xlo);
        const uint32_t dbase  = (lane < 16 ? hbase0 : lbase0) + (lane & 15) * 16;
#pragma unroll
        for (int r = 0; r < 8; ++r) {
            const int row = r0 + r;
            const char* src = (const char*)g_xs + (size_t)selid[row] * 512 + lane * 16;
            uint32_t dst = dbase + (uint32_t)(row * (BPITCH * 2));
            asm volatile("cp.async.ca.shared.global [%0], [%1], 16;"
                         :: "r"(dst), "l"(src));
        }
        asm volatile("cp.async.commit_group;");
        asm volatile("cp.async.wait_group 0;");
    }
    __syncthreads();

    // --- Gram, 3 tiles: w0 diag(0,0) A=B aliased, w1 diag(16,16), w2 offdiag ---
    const uint32_t hbase = smem_u32(xhi);
    const uint32_t lbase = smem_u32(xlo);
    const int p = lane >> 2;
    const int q = lane & 3;
    float c0f[4] = {0.f, 0.f, 0.f, 0.f};
    float c1f[4] = {0.f, 0.f, 0.f, 0.f};

    if (wrp < 2) {
        const int m0 = wrp * 16;
        const int rsel = lane >> 3, rin = lane & 7;
        const uint32_t a_off = (uint32_t)((m0 + (rsel & 1) * 8 + rin) * BPITCH
                                          + (rsel >> 1) * 8) * 2;
#pragma unroll
        for (int kc = 0; kc < 8; ++kc) {
            uint32_t ah[4], al[4];
            ldmatrix_x4(ah, hbase + a_off + kc * 32);
            ldmatrix_x4(al, lbase + a_off + kc * 32);
            uint32_t bh0[2] = {ah[0], ah[2]}, bh1[2] = {ah[1], ah[3]};
            uint32_t bl0[2] = {al[0], al[2]}, bl1[2] = {al[1], al[3]};
            mma_bf16(c0f, ah, bh0); mma_bf16(c0f, ah, bl0); mma_bf16(c0f, al, bh0);
            mma_bf16(c1f, ah, bh1); mma_bf16(c1f, ah, bl1); mma_bf16(c1f, al, bh1);
        }
        if (p == 2 * q)     { ssq[m0 + p] = c0f[0]; ssq[m0 + p + 8] = c1f[2]; }
        if (p == 2 * q + 1) { ssq[m0 + p] = c0f[1]; ssq[m0 + p + 8] = c1f[3]; }
    } else if (wrp == 2) {
        const int rsel = lane >> 3, rin = lane & 7;
        const uint32_t a_off = (uint32_t)(((rsel & 1) * 8 + rin) * BPITCH
                                          + (rsel >> 1) * 8) * 2;
        const uint32_t b_off = (uint32_t)((16 + (rsel >> 1) * 8 + rin) * BPITCH
                                          + (rsel & 1) * 8) * 2;
#pragma unroll
        for (int kc = 0; kc < 8; ++kc) {
            uint32_t ah[4], al[4], bh[4], bl[4];
            ldmatrix_x4(ah, hbase + a_off + kc * 32);
            ldmatrix_x4(al, lbase + a_off + kc * 32);
            ldmatrix_x4(bh, hbase + b_off + kc * 32);
            ldmatrix_x4(bl, lbase + b_off + kc * 32);
            mma_bf16(c0f, ah, &bh[0]); mma_bf16(c0f, ah, &bl[0]); mma_bf16(c0f, al, &bh[0]);
            mma_bf16(c1f, ah, &bh[2]); mma_bf16(c1f, ah, &bl[2]); mma_bf16(c1f, al, &bh[2]);
        }
    }
    __syncthreads();   // ssq visible to all

    // --- dist partials ---
    if (wrp < 2) {
        const int m0 = wrp * 16;
        const int b0 = m0 + 2 * q, b1 = b0 + 1, b2 = b0 + 8, b3 = b2 + 1;
        const float w0 = selw[b0], w1 = selw[b1], w2 = selw[b2], w3 = selw[b3];
        const float s0 = ssq[b0], s1 = ssq[b1], s2 = ssq[b2], s3 = ssq[b3];
        const float sqa  = ssq[m0 + p];
        const float sqa8 = ssq[m0 + p + 8];

        float d, part = 0.f, part8 = 0.f;
        d = sqa  + s0 - 2.f * c0f[0]; part  = fmaf(w0, (d > 0.f) ? sqrt_approx(d) : 0.f, part);
        d = sqa  + s1 - 2.f * c0f[1]; part  = fmaf(w1, (d > 0.f) ? sqrt_approx(d) : 0.f, part);
        d = sqa  + s2 - 2.f * c1f[0]; part  = fmaf(w2, (d > 0.f) ? sqrt_approx(d) : 0.f, part);
        d = sqa  + s3 - 2.f * c1f[1]; part  = fmaf(w3, (d > 0.f) ? sqrt_approx(d) : 0.f, part);
        d = sqa8 + s0 - 2.f * c0f[2]; part8 = fmaf(w0, (d > 0.f) ? sqrt_approx(d) : 0.f, part8);
        d = sqa8 + s1 - 2.f * c0f[3]; part8 = fmaf(w1, (d > 0.f) ? sqrt_approx(d) : 0.f, part8);
        d = sqa8 + s2 - 2.f * c1f[2]; part8 = fmaf(w2, (d > 0.f) ? sqrt_approx(d) : 0.f, part8);
        d = sqa8 + s3 - 2.f * c1f[3]; part8 = fmaf(w3, (d > 0.f) ? sqrt_approx(d) : 0.f, part8);

        part  += __shfl_down_sync(0xffffffffu, part, 2);
        part  += __shfl_down_sync(0xffffffffu, part, 1);
        part8 += __shfl_down_sync(0xffffffffu, part8, 2);
        part8 += __shfl_down_sync(0xffffffffu, part8, 1);
        if (q == 0) { sdA[m0 + p] = part; sdA[m0 + p + 8] = part8; }
    } else if (wrp == 2) {
        const int cA = 16 + 2 * q, cB = cA + 1, cC = cA + 8, cD = cC + 1;
        const float wA = selw[cA], wB = selw[cB], wC = selw[cC], wD = selw[cD];
        const float sA = ssq[cA], sB = ssq[cB], sC = ssq[cC], sD = ssq[cD];
        const float sqa  = ssq[p];
        const float sqa8 = ssq[p + 8];
        const float wp   = selw[p];
        const float wp8  = selw[p + 8];

        float d;
        d = sqa  + sA - 2.f * c0f[0]; float dpA = (d > 0.f) ? sqrt_approx(d) : 0.f;
        d = sqa  + sB - 2.f * c0f[1]; float dpB = (d > 0.f) ? sqrt_approx(d) : 0.f;
        d = sqa  + sC - 2.f * c1f[0]; float dpC = (d > 0.f) ? sqrt_approx(d) : 0.f;
        d = sqa  + sD - 2.f * c1f[1]; float dpD = (d > 0.f) ? sqrt_approx(d) : 0.f;
        d = sqa8 + sA - 2.f * c0f[2]; float d8A = (d > 0.f) ? sqrt_approx(d) : 0.f;
        d = sqa8 + sB - 2.f * c0f[3]; float d8B = (d > 0.f) ? sqrt_approx(d) : 0.f;
        d = sqa8 + sC - 2.f * c1f[2]; float d8C = (d > 0.f) ? sqrt_approx(d) : 0.f;
        d = sqa8 + sD - 2.f * c1f[3]; float d8D = (d > 0.f) ? sqrt_approx(d) : 0.f;

        float part  = wA * dpA + wB * dpB + wC * dpC + wD * dpD;
        float part8 = wA * d8A + wB * d8B + wC * d8C + wD * d8D;
        part  += __shfl_down_sync(0xffffffffu, part, 2);
        part  += __shfl_down_sync(0xffffffffu, part, 1);
        part8 += __shfl_down_sync(0xffffffffu, part8, 2);
        part8 += __shfl_down_sync(0xffffffffu, part8, 1);
        if (q == 0) { sdB[p] = part; sdB[p + 8] = part8; }

        float colA = wp * dpA + wp8 * d8A;
        float colB = wp * dpB + wp8 * d8B;
        float colC = wp * dpC + wp8 * d8C;
        float colD = wp * dpD + wp8 * d8D;
#pragma unroll
        for (int off = 4; off <= 16; off <<= 1) {
            colA += __shfl_xor_sync(0xffffffffu, colA, off);
            colB += __shfl_xor_sync(0xffffffffu, colB, off);
            colC += __shfl_xor_sync(0xffffffffu, colC, off);
            colD += __shfl_xor_sync(0xffffffffu, colD, off);
        }
        if (lane < 4) {
            *(float2*)&sdB[16 + 2 * lane] = make_float2(colA, colB);
            *(float2*)&sdB[24 + 2 * lane] = make_float2(colC, colD);
        }
    }
    __syncthreads();

    // --- softmax(-dist) * tw, renormalized; emit rel hi/lo (warp 0) ---
    if (tid < 32) {
        float v = sdA[tid] + sdB[tid];
        float m = v;
#pragma unroll
        for (int off = 16; off; off >>= 1)
            m = fminf(m, __shfl_xor_sync(0xffffffffu, m, off));
        float r = __expf(m - v) * selw[tid];
        float s = r;
#pragma unroll
        for (int off = 16; off; off >>= 1)
            s += __shfl_xor_sync(0xffffffffu, s, off);
        float rr = __fdividef(r, s);
        uint32_t bits = __float_as_uint(rr);
        srelh[tid] = (unsigned short)(bits >> 16);
        float rl = rr - __uint_as_float(bits & 0xffff0000u);
        srell[tid] = __bfloat16_as_ushort(__float2bfloat16_rn(rl));
    }
    __syncthreads();

    // --- aggregation: out^T = X^T @ rel via mma; warp w -> dout [32w, 32w+32) ---
    {
        const uint32_t* relh32 = (const uint32_t*)srelh;
        const uint32_t* rell32 = (const uint32_t*)srell;
        const int d0 = wrp * 32;
        const int g = lane >> 3, rin = lane & 7;

        float cacc[2][4];
#pragma unroll
        for (int i = 0; i < 2; ++i)
#pragma unroll
            for (int j = 0; j < 4; ++j) cacc[i][j] = 0.f;

#pragma unroll
        for (int kc = 0; kc < 2; ++kc) {
            uint32_t bh[2], bl[2];
            bh[0] = relh32[kc * 8 + q];
            bh[1] = relh32[kc * 8 + 4 + q];
            bl[0] = rell32[kc * 8 + q];
            bl[1] = rell32[kc * 8 + 4 + q];

#pragma unroll
            for (int mt = 0; mt < 2; ++mt) {
                uint32_t aoff = (uint32_t)(((kc * 16 + (g >> 1) * 8 + rin) * BPITCH
                                            + d0 + mt * 16 + (g & 1) * 8) * 2);
                uint32_t ah[4], al[4];
                ldmatrix_x4_trans(ah, hbase + aoff);
                ldmatrix_x4_trans(al, lbase + aoff);

                mma_bf16(cacc[mt], ah, bh);
                mma_bf16(cacc[mt], ah, bl);
                mma_bf16(cacc[mt], al, bh);
            }
        }

        if (q == 0) {
#pragma unroll
            for (int mt = 0; mt < 2; ++mt) {
                int dd = d0 + mt * 16 + p;
                out[(size_t)node * DOUT + dd]     = cacc[mt][0] + bias[dd];
                out[(size_t)node * DOUT + dd + 8] = cacc[mt][2] + bias[dd + 8];
            }
        }
    }
}

// ---------------------------------------------------------------------------
// Launch (2-kernel chain)
// ---------------------------------------------------------------------------
extern "C" void kernel_launch(void* const* d_in, const int* in_sizes, int n_in,
                              void* d_out, int out_size)
{
    const float* feat   = (const float*)d_in[0];
    const float* ew     = (const float*)d_in[1];
    const float* weight = (const float*)d_in[2];
    const float* bias   = (const float*)d_in[3];
    const int*   nbr    = (const int*)  d_in[4];
    float*       out    = (float*)d_out;

    int n = in_sizes[0] / DIN;

    gemm_kernel<<<(n + 127) / 128, 256>>>(feat, weight, n);
    node_kernel<<<n, 128>>>(ew, nbr, bias, out, n);
}